// round 2
// baseline (speedup 1.0000x reference)
#include <cuda_runtime.h>
#include <cuda_bf16.h>
#include <cstdint>

// ---------------------------------------------------------------------------
// Problem constants
// ---------------------------------------------------------------------------
#define HH    192
#define WW    192
#define NPIX  (HH*WW)          // 36864
#define NB    8                // 2 halves * batch 4
#define CIN   128              // DIM_H
#define NHEAD 4
#define HD    32               // head dim

typedef unsigned long long ull;

// ---------------------------------------------------------------------------
// Device scratch (static __device__ arrays: allowed; no allocs)
// q/k/v layout: [n(8)][head(4)][pixel(36864)][hd(32)]  -> 128B per pixel/head
// ---------------------------------------------------------------------------
__device__ float g_q[8*4*NPIX*32];
__device__ float g_k[8*4*NPIX*32];
__device__ float g_v[8*4*NPIX*32];
__device__ float g_wt[3*128*128];   // [pass][k][o] transposed qkv weights
__device__ float g_lw[4*9*32];      // [head][tap][hd] lepe weights
__device__ float g_lb[4*32];        // [head][hd] lepe bias
__device__ float g_bias[4*16];      // [head][i*4+j] attention bias

// ---------------------------------------------------------------------------
// packed f32x2 helpers (FFMA2: 2 FMAs per instruction on sm_103a)
// ---------------------------------------------------------------------------
__device__ __forceinline__ ull pk2(float a, float b) {
    ull r; asm("mov.b64 %0, {%1, %2};" : "=l"(r) : "f"(a), "f"(b)); return r;
}
__device__ __forceinline__ ull dup2(float a) {
    ull r; asm("mov.b64 %0, {%1, %1};" : "=l"(r) : "f"(a)); return r;
}
__device__ __forceinline__ ull ffma2(ull a, ull b, ull c) {
    ull d; asm("fma.rn.f32x2 %0, %1, %2, %3;" : "=l"(d) : "l"(a), "l"(b), "l"(c)); return d;
}
__device__ __forceinline__ void upk2(ull v, float& a, float& b) {
    asm("mov.b64 {%0, %1}, %2;" : "=f"(a), "=f"(b) : "l"(v));
}

// ---------------------------------------------------------------------------
// Kernel 0: weight / bias re-layout (tiny)
// ---------------------------------------------------------------------------
__global__ void prep_kernel(const float* __restrict__ qkv_w,
                            const float* __restrict__ lepe_w,
                            const float* __restrict__ lepe_b,
                            const float* __restrict__ bias_table,
                            const int*   __restrict__ rel_idx)
{
    int t = threadIdx.x;
    // g_wt[pass][k][o] = qkv_w[pass*128+o][k]
    for (int idx = t; idx < 3*128*128; idx += 256) {
        int pass = idx >> 14;
        int r    = idx & 16383;
        int k    = r >> 7;
        int o    = r & 127;
        g_wt[idx] = qkv_w[(pass*128 + o)*128 + k];
    }
    // g_lw[head][tap][hd] = lepe_w[(hd*4+head)*9 + tap]
    for (int idx = t; idx < 4*9*32; idx += 256) {
        int head = idx / 288;
        int r    = idx % 288;
        int tap  = r >> 5;
        int hd   = r & 31;
        g_lw[idx] = lepe_w[(hd*4 + head)*9 + tap];
    }
    // g_lb[head][hd] = lepe_b[hd*4+head]
    if (t < 128) {
        int head = t >> 5, hd = t & 31;
        g_lb[t] = lepe_b[hd*4 + head];
    }
    // g_bias[head][i*4+j] = bias_table[rel_idx[i*4+j]*4 + head]
    if (t < 64) {
        int head = t >> 4, ij = t & 15;
        g_bias[t] = bias_table[rel_idx[ij]*4 + head];
    }
}

// ---------------------------------------------------------------------------
// Kernel 1: QKV 1x1 conv as a tiled GEMM.
// CTA: 256 threads, 128 pixels x 384 out channels (3 passes of 128).
// Thread tile: 8 pixels x 8 channels, packed-f32x2 accumulation.
// smem: xs[k=128][pix=128], ws[k=128][o=128]  (= 128 KB dynamic)
// ---------------------------------------------------------------------------
__global__ void __launch_bounds__(256)
qkv_kernel(const float* __restrict__ x)
{
    extern __shared__ __align__(16) float sm[];
    float* xs = sm;            // 16384 floats
    float* ws = sm + 16384;    // 16384 floats
    float4* xs4 = (float4*)xs;
    float4* ws4 = (float4*)ws;

    const int tid  = threadIdx.x;
    const int n    = blockIdx.y;        // 0..7
    const int half = n >> 2;
    const int b    = n & 3;
    const int p0   = blockIdx.x * 128;  // pixel block

    // load xs[k][pix]: channel i is a contiguous run of pixels in global
    const float* xb = x + ((size_t)(b*256 + half*128)) * NPIX + p0;
    #pragma unroll
    for (int it = 0; it < 16; ++it) {
        int idx = tid + it*256;            // float4 index 0..4095
        int row = idx >> 5;                // input channel k
        int col = idx & 31;                // pixel quad
        xs4[idx] = __ldg((const float4*)(xb + (size_t)row * NPIX) + col);
    }

    const int tx = tid & 15;   // channel group
    const int ty = tid >> 4;   // pixel group

    for (int pass = 0; pass < 3; ++pass) {
        __syncthreads();   // previous pass done reading ws
        const float4* wt4 = (const float4*)(g_wt + pass*16384);
        #pragma unroll
        for (int it = 0; it < 16; ++it) {
            int idx = tid + it*256;
            ws4[idx] = __ldg(wt4 + idx);
        }
        __syncthreads();

        ull acc[8][4];
        #pragma unroll
        for (int p = 0; p < 8; ++p)
            #pragma unroll
            for (int c = 0; c < 4; ++c) acc[p][c] = dup2(0.0f);

        #pragma unroll 16
        for (int k = 0; k < 128; ++k) {
            float4 xA = xs4[k*32 + ty];
            float4 xB = xs4[k*32 + ty + 16];
            float4 wA = ws4[k*32 + tx];
            float4 wB = ws4[k*32 + tx + 16];
            ull w0 = pk2(wA.x, wA.y);
            ull w1 = pk2(wA.z, wA.w);
            ull w2 = pk2(wB.x, wB.y);
            ull w3 = pk2(wB.z, wB.w);
            float xv[8] = {xA.x, xA.y, xA.z, xA.w, xB.x, xB.y, xB.z, xB.w};
            #pragma unroll
            for (int p = 0; p < 8; ++p) {
                ull xd = dup2(xv[p]);
                acc[p][0] = ffma2(xd, w0, acc[p][0]);
                acc[p][1] = ffma2(xd, w1, acc[p][1]);
                acc[p][2] = ffma2(xd, w2, acc[p][2]);
                acc[p][3] = ffma2(xd, w3, acc[p][3]);
            }
        }

        // store to scratch: channels tx*4+e (heads e, hd=tx) and 64+tx*4+e (hd=16+tx)
        float* dst = (pass == 0) ? g_q : (pass == 1) ? g_k : g_v;
        const size_t nb = (size_t)n * 4;
        #pragma unroll
        for (int p8 = 0; p8 < 8; ++p8) {
            int pg = p8 >> 2, pe = p8 & 3;
            int p  = p0 + pg*64 + ty*4 + pe;
            #pragma unroll
            for (int cg = 0; cg < 2; ++cg) {
                int hd = cg*16 + tx;
                float f0, f1, f2, f3;
                upk2(acc[p8][cg*2 + 0], f0, f1);   // heads 0,1
                upk2(acc[p8][cg*2 + 1], f2, f3);   // heads 2,3
                dst[((nb + 0)*NPIX + p)*32 + hd] = f0;
                dst[((nb + 1)*NPIX + p)*32 + hd] = f1;
                dst[((nb + 2)*NPIX + p)*32 + hd] = f2;
                dst[((nb + 3)*NPIX + p)*32 + hd] = f3;
            }
        }
    }
}

// ---------------------------------------------------------------------------
// Kernel 2: window attention + LePE + output scatter.
// CTA: (tile_x, tile_y, n*4+head), 16x16 pixel tile, 256 threads.
// Thread = (window w: 0..63, token i: 0..3).
// v tile (with 1px halo) staged in smem, stride padded to 36 floats.
// ---------------------------------------------------------------------------
#define VSTRIDE 36

__global__ void __launch_bounds__(256)
attn_kernel(float* __restrict__ out)
{
    __shared__ __align__(16) float vs[324 * VSTRIDE];   // 18x18 halo tile
    __shared__ __align__(16) float ws9[9 * 32];         // lepe weights for this head
    __shared__ __align__(16) float bsm[32];             // lepe bias
    __shared__ __align__(16) float bias_sm[16];         // attention bias [i][j]

    const int nh   = blockIdx.z;          // n*4 + head
    const int n    = nh >> 2;
    const int head = nh & 3;
    const int half = n >> 2;
    const int b    = n & 3;
    const int y0   = blockIdx.y * 16;
    const int x0   = blockIdx.x * 16;
    const int tid  = threadIdx.x;

    const float* vg = g_v + (size_t)nh * NPIX * 32;

    // stage v halo tile (zero-padded at image border)
    for (int idx = tid; idx < 324*8; idx += 256) {
        int pix = idx >> 3;
        int c8  = idx & 7;
        int ly  = pix / 18;
        int lx  = pix - ly*18;
        int gy  = y0 + ly - 1;
        int gx  = x0 + lx - 1;
        float4 vv = make_float4(0.f, 0.f, 0.f, 0.f);
        if (gy >= 0 && gy < HH && gx >= 0 && gx < WW)
            vv = __ldg((const float4*)(vg + ((size_t)(gy*WW + gx))*32) + c8);
        *(float4*)(vs + pix*VSTRIDE + c8*4) = vv;
    }
    // stage per-head constants (blockDim = 256, so use loops / low-tid slices)
    for (int idx = tid; idx < 288; idx += 256)
        ws9[idx] = g_lw[head*288 + idx];
    if (tid < 32)
        bsm[tid] = g_lb[head*32 + tid];
    else if (tid < 48)
        bias_sm[tid - 32] = g_bias[head*16 + (tid - 32)];
    __syncthreads();

    const int w  = tid >> 2;
    const int i  = tid & 3;
    const int wy = w >> 3, wx = w & 7;
    const int sy = i >> 1, sx = i & 1;
    const int iy = wy*2 + sy, ix = wx*2 + sx;   // tile coords of this token
    const int gy = y0 + iy,  gx = x0 + ix;

    // ---- logits: q_i . k_j over 32 dims ----
    const float* qg = g_q + ((size_t)nh * NPIX + (size_t)gy*WW + gx) * 32;
    float qr[32];
    #pragma unroll
    for (int c8 = 0; c8 < 8; ++c8) {
        float4 qv = __ldg((const float4*)qg + c8);
        qr[c8*4+0] = qv.x; qr[c8*4+1] = qv.y; qr[c8*4+2] = qv.z; qr[c8*4+3] = qv.w;
    }
    const float* kgbase = g_k + ((size_t)nh * NPIX + (size_t)(y0 + wy*2)*WW + (x0 + wx*2)) * 32;
    float lg[4];
    #pragma unroll
    for (int j = 0; j < 4; ++j) {
        const float* kg = kgbase + ((size_t)((j >> 1)*WW + (j & 1))) * 32;
        float s = 0.f;
        #pragma unroll
        for (int c8 = 0; c8 < 8; ++c8) {
            float4 kv = __ldg((const float4*)kg + c8);
            s = fmaf(qr[c8*4+0], kv.x, s);
            s = fmaf(qr[c8*4+1], kv.y, s);
            s = fmaf(qr[c8*4+2], kv.z, s);
            s = fmaf(qr[c8*4+3], kv.w, s);
        }
        lg[j] = s;
    }
    const float scale = 0.17677669529663687f;  // 1/sqrt(32)
    #pragma unroll
    for (int j = 0; j < 4; ++j) lg[j] = lg[j]*scale + bias_sm[i*4 + j];

    float m  = fmaxf(fmaxf(lg[0], lg[1]), fmaxf(lg[2], lg[3]));
    float a0 = expf(lg[0] - m);
    float a1 = expf(lg[1] - m);
    float a2 = expf(lg[2] - m);
    float a3 = expf(lg[3] - m);
    float inv = 1.0f / (a0 + a1 + a2 + a3);
    a0 *= inv; a1 *= inv; a2 *= inv; a3 *= inv;

    // ---- out_i = sum_j a_j v_j + lepe_i ----
    int vj0 = ((wy*2 + 0 + 1)*18 + (wx*2 + 0 + 1)) * VSTRIDE;
    int vj1 = ((wy*2 + 0 + 1)*18 + (wx*2 + 1 + 1)) * VSTRIDE;
    int vj2 = ((wy*2 + 1 + 1)*18 + (wx*2 + 0 + 1)) * VSTRIDE;
    int vj3 = ((wy*2 + 1 + 1)*18 + (wx*2 + 1 + 1)) * VSTRIDE;

    const size_t ob = ((size_t)(b*256 + half*128 + head)) * NPIX + (size_t)gy*WW + gx;

    #pragma unroll
    for (int c8 = 0; c8 < 8; ++c8) {
        float4 v0 = *(const float4*)(vs + vj0 + c8*4);
        float4 v1 = *(const float4*)(vs + vj1 + c8*4);
        float4 v2 = *(const float4*)(vs + vj2 + c8*4);
        float4 v3 = *(const float4*)(vs + vj3 + c8*4);

        float ox = a0*v0.x; ox = fmaf(a1, v1.x, ox); ox = fmaf(a2, v2.x, ox); ox = fmaf(a3, v3.x, ox);
        float oy = a0*v0.y; oy = fmaf(a1, v1.y, oy); oy = fmaf(a2, v2.y, oy); oy = fmaf(a3, v3.y, oy);
        float oz = a0*v0.z; oz = fmaf(a1, v1.z, oz); oz = fmaf(a2, v2.z, oz); oz = fmaf(a3, v3.z, oz);
        float ow = a0*v0.w; ow = fmaf(a1, v1.w, ow); ow = fmaf(a2, v2.w, ow); ow = fmaf(a3, v3.w, ow);

        // LePE: 3x3 depthwise conv around pixel (iy, ix); center in vs is (iy+1, ix+1)
        #pragma unroll
        for (int t = 0; t < 9; ++t) {
            int dy = t / 3, dx = t - dy*3;
            float4 vv = *(const float4*)(vs + ((iy + dy)*18 + (ix + dx))*VSTRIDE + c8*4);
            float4 wv = *(const float4*)(ws9 + t*32 + c8*4);
            ox = fmaf(wv.x, vv.x, ox);
            oy = fmaf(wv.y, vv.y, oy);
            oz = fmaf(wv.z, vv.z, oz);
            ow = fmaf(wv.w, vv.w, ow);
        }
        float4 bb = *(const float4*)(bsm + c8*4);
        ox += bb.x; oy += bb.y; oz += bb.z; ow += bb.w;

        // channels hd = c8*4+e -> global channel (hd*4 + head), stride 4*NPIX
        out[ob + (size_t)(c8*4 + 0) * 4 * NPIX] = ox;
        out[ob + (size_t)(c8*4 + 1) * 4 * NPIX] = oy;
        out[ob + (size_t)(c8*4 + 2) * 4 * NPIX] = oz;
        out[ob + (size_t)(c8*4 + 3) * 4 * NPIX] = ow;
    }
}

// ---------------------------------------------------------------------------
// Launcher
// ---------------------------------------------------------------------------
extern "C" void kernel_launch(void* const* d_in, const int* in_sizes, int n_in,
                              void* d_out, int out_size)
{
    const float* x          = (const float*)d_in[0];
    const float* qkv_w      = (const float*)d_in[1];
    const float* lepe_w     = (const float*)d_in[2];
    const float* lepe_b     = (const float*)d_in[3];
    const float* bias_table = (const float*)d_in[4];
    const int*   rel_idx    = (const int*)  d_in[5];
    float* out = (float*)d_out;

    cudaFuncSetAttribute(qkv_kernel, cudaFuncAttributeMaxDynamicSharedMemorySize, 131072);

    prep_kernel<<<1, 256>>>(qkv_w, lepe_w, lepe_b, bias_table, rel_idx);

    dim3 g1(NPIX/128, NB);           // 288 x 8
    qkv_kernel<<<g1, 256, 131072>>>(x);

    dim3 g2(WW/16, HH/16, NB*NHEAD); // 12 x 12 x 32
    attn_kernel<<<g2, 256>>>(out);
}

// round 4
// speedup vs baseline: 1.1875x; 1.1875x over previous
#include <cuda_runtime.h>
#include <cuda_bf16.h>
#include <cstdint>

// ---------------------------------------------------------------------------
// Problem constants
// ---------------------------------------------------------------------------
#define HH    192
#define WW    192
#define NPIX  (HH*WW)          // 36864
#define NB    8                // 2 halves * batch 4
#define NHEAD 4

// ---------------------------------------------------------------------------
// Device scratch
// q/k/v layout: [n(8)][head(4)][pixel(36864)][hd(32)]
// ---------------------------------------------------------------------------
__device__ float g_q[8*4*NPIX*32];
__device__ float g_k[8*4*NPIX*32];
__device__ float g_v[8*4*NPIX*32];
__device__ float g_lw[4*9*32];      // [head][tap][hd] lepe weights
__device__ float g_lb[4*32];        // [head][hd] lepe bias
__device__ float g_bias[4*16];      // [head][i*4+j] attention bias

// ---------------------------------------------------------------------------
// tf32 helpers (base-ISA mma.sync — no 'a'-suffix features)
// ---------------------------------------------------------------------------
__device__ __forceinline__ uint32_t cvt_tf32(float v) {
    uint32_t t;
    asm("cvt.rna.tf32.f32 %0, %1;" : "=r"(t) : "f"(v));
    return t;
}
__device__ __forceinline__ void mma_tf32(float* c, const uint4& a, const uint2& b) {
    asm volatile(
        "mma.sync.aligned.m16n8k8.row.col.f32.tf32.tf32.f32 "
        "{%0,%1,%2,%3}, {%4,%5,%6,%7}, {%8,%9}, {%0,%1,%2,%3};"
        : "+f"(c[0]), "+f"(c[1]), "+f"(c[2]), "+f"(c[3])
        : "r"(a.x), "r"(a.y), "r"(a.z), "r"(a.w), "r"(b.x), "r"(b.y));
}

// smem layout (floats):
//   A frag  @ 0      : 16384 floats (128 pix x 128 k, fragment-major + XOR swizzle)
//   B buf0  @ 16384  : 16 ksteps x (16 ntiles x 64 + 2 pad) = 16416 floats
//   B buf1  @ 32800  : 16416 floats
#define B_KSTRIDE 1026
#define SMF_B0 16384
#define SMF_B1 (16384 + 16*B_KSTRIDE)          // 32800
#define SM_TOT ((SMF_B1 + 16*B_KSTRIDE) * 4)   // 196864 bytes

// ---------------------------------------------------------------------------
// Kernel 0: lepe / bias re-layout (tiny)
// ---------------------------------------------------------------------------
__global__ void prep_kernel(const float* __restrict__ lepe_w,
                            const float* __restrict__ lepe_b,
                            const float* __restrict__ bias_table,
                            const int*   __restrict__ rel_idx)
{
    int t = threadIdx.x;
    for (int idx = t; idx < 4*9*32; idx += 256) {
        int head = idx / 288;
        int r    = idx % 288;
        int tap  = r >> 5;
        int hd   = r & 31;
        g_lw[idx] = lepe_w[(hd*4 + head)*9 + tap];
    }
    if (t < 128) {
        int head = t >> 5, hd = t & 31;
        g_lb[t] = lepe_b[hd*4 + head];
    }
    if (t < 64) {
        int head = t >> 4, ij = t & 15;
        g_bias[t] = bias_table[rel_idx[ij]*4 + head];
    }
}

// ---------------------------------------------------------------------------
// B staging: weights [o(128)][k(128)] fp32 -> tf32 fragment-major
// fragment (kstep, ntile): lane holds b0 = B[k8+tg][n0+g], b1 = B[k8+tg+4][n0+g]
// float idx = kstep*1026 + ntile*64 + lane*2 + r
// ---------------------------------------------------------------------------
__device__ __forceinline__ void stage_b_frag(uint32_t* __restrict__ Bs,
                                             const float* __restrict__ w, int tid)
{
    #pragma unroll
    for (int it = 0; it < 16; ++it) {
        int i  = it*256 + tid;
        int o  = i >> 5;          // output channel (n)
        int k4 = i & 31;          // float4 index along k
        float4 v = __ldg((const float4*)(w + (size_t)o*128) + k4);
        int kstep = k4 >> 1, r = k4 & 1;
        uint32_t base = (uint32_t)(kstep*B_KSTRIDE + (o>>3)*64 + (o&7)*8 + r);
        Bs[base + 0] = cvt_tf32(v.x);
        Bs[base + 2] = cvt_tf32(v.y);
        Bs[base + 4] = cvt_tf32(v.z);
        Bs[base + 6] = cvt_tf32(v.w);
    }
}

// ---------------------------------------------------------------------------
// One N=128 pass: 16 ksteps of m16n8k8 tf32 mma, then epilogue to dst
// warp tile: 32 (M) x 64 (N); acc[2][8][4]
// ---------------------------------------------------------------------------
__device__ __forceinline__ void do_pass(const uint32_t* __restrict__ As,
                                        const uint32_t* __restrict__ Bs,
                                        float* __restrict__ dst,
                                        int warp_m, int warp_n, int lane,
                                        int p0, size_t n4)
{
    float acc[2][8][4];
    #pragma unroll
    for (int i = 0; i < 2; ++i)
        #pragma unroll
        for (int j = 0; j < 8; ++j)
            #pragma unroll
            for (int e = 0; e < 4; ++e) acc[i][j][e] = 0.0f;

    #pragma unroll
    for (int kstep = 0; kstep < 16; ++kstep) {
        uint4 a[2];
        #pragma unroll
        for (int i = 0; i < 2; ++i) {
            uint32_t u = (uint32_t)((kstep*8 + warp_m*2 + i)*32 + lane);
            u ^= (u >> 3) & 7;
            a[i] = *(const uint4*)(As + (size_t)u*4);
        }
        uint2 bf[8];
        #pragma unroll
        for (int j = 0; j < 8; ++j)
            bf[j] = *(const uint2*)(Bs + kstep*B_KSTRIDE + (warp_n*8 + j)*64 + lane*2);

        #pragma unroll
        for (int i = 0; i < 2; ++i)
            #pragma unroll
            for (int j = 0; j < 8; ++j)
                mma_tf32(acc[i][j], a[i], bf[j]);
    }

    // epilogue: C[m][o] -> dst[(n4 + (o&3))*NPIX + p][o>>2]
    const int g  = lane >> 2;
    const int tg = lane & 3;
    #pragma unroll
    for (int i = 0; i < 2; ++i) {
        int p = p0 + warp_m*32 + i*16 + g;
        #pragma unroll
        for (int j = 0; j < 8; ++j) {
            int o0 = warp_n*64 + j*8 + 2*tg;
            int h0 = o0 & 3, h1 = (o0 + 1) & 3;
            int hd = o0 >> 2;
            dst[((n4 + h0)*NPIX + p    )*32 + hd] = acc[i][j][0];
            dst[((n4 + h1)*NPIX + p    )*32 + hd] = acc[i][j][1];
            dst[((n4 + h0)*NPIX + p + 8)*32 + hd] = acc[i][j][2];
            dst[((n4 + h1)*NPIX + p + 8)*32 + hd] = acc[i][j][3];
        }
    }
}

// ---------------------------------------------------------------------------
// Kernel 1: QKV 1x1 conv as tf32 mma.sync GEMM.
// CTA: 256 threads (8 warps, 4M x 2N), M=128 pixels, K=128, 3 passes of N=128.
// ---------------------------------------------------------------------------
__global__ void __launch_bounds__(256)
qkv_hmma_kernel(const float* __restrict__ x, const float* __restrict__ qkv_w)
{
    extern __shared__ __align__(16) float smf[];
    uint32_t* As  = (uint32_t*)smf;
    uint32_t* Bs0 = (uint32_t*)(smf + SMF_B0);
    uint32_t* Bs1 = (uint32_t*)(smf + SMF_B1);

    const int tid    = threadIdx.x;
    const int lane   = tid & 31;
    const int wid    = tid >> 5;
    const int warp_m = wid >> 1;    // 0..3
    const int warp_n = wid & 1;     // 0..1
    const int n      = blockIdx.y;
    const int half   = n >> 2;
    const int b      = n & 3;
    const int p0     = blockIdx.x * 128;
    const size_t n4  = (size_t)n * 4;

    // ---- stage A: x (planar [ch][pix]) -> tf32 fragment-major + swizzle ----
    {
        const int pix = tid & 127;
        const int kh  = tid >> 7;                     // k-half 0..1
        const float* xb = x + ((size_t)(b*256 + half*128 + kh*64)) * NPIX + p0 + pix;
        const int mtile   = pix >> 4;
        const int g       = pix & 7;
        const int rowhalf = (pix >> 3) & 1;
        #pragma unroll 8
        for (int k2 = 0; k2 < 64; ++k2) {
            int k = kh*64 + k2;
            float v = __ldg(xb + (size_t)k2 * NPIX);
            int kstep = k >> 3, tg = k & 3, colhalf = (k >> 2) & 1;
            uint32_t u = (uint32_t)((kstep*8 + mtile)*32 + g*4 + tg);
            u ^= (u >> 3) & 7;
            As[u*4 + colhalf*2 + rowhalf] = cvt_tf32(v);
        }
    }
    stage_b_frag(Bs0, qkv_w, tid);               // q weights
    __syncthreads();

    stage_b_frag(Bs1, qkv_w + 16384, tid);       // k weights (overlaps pass 0)
    do_pass(As, Bs0, g_q, warp_m, warp_n, lane, p0, n4);
    __syncthreads();                              // Bs1 ready; Bs0 free

    stage_b_frag(Bs0, qkv_w + 32768, tid);       // v weights (overlaps pass 1)
    do_pass(As, Bs1, g_k, warp_m, warp_n, lane, p0, n4);
    __syncthreads();                              // Bs0 ready

    do_pass(As, Bs0, g_v, warp_m, warp_n, lane, p0, n4);
}

// ---------------------------------------------------------------------------
// Kernel 2: window attention + LePE + output scatter (unchanged, passing)
// ---------------------------------------------------------------------------
#define VSTRIDE 36

__global__ void __launch_bounds__(256)
attn_kernel(float* __restrict__ out)
{
    __shared__ __align__(16) float vs[324 * VSTRIDE];   // 18x18 halo tile
    __shared__ __align__(16) float ws9[9 * 32];
    __shared__ __align__(16) float bsm[32];
    __shared__ __align__(16) float bias_sm[16];

    const int nh   = blockIdx.z;
    const int n    = nh >> 2;
    const int head = nh & 3;
    const int half = n >> 2;
    const int b    = n & 3;
    const int y0   = blockIdx.y * 16;
    const int x0   = blockIdx.x * 16;
    const int tid  = threadIdx.x;

    const float* vg = g_v + (size_t)nh * NPIX * 32;

    for (int idx = tid; idx < 324*8; idx += 256) {
        int pix = idx >> 3;
        int c8  = idx & 7;
        int ly  = pix / 18;
        int lx  = pix - ly*18;
        int gy  = y0 + ly - 1;
        int gx  = x0 + lx - 1;
        float4 vv = make_float4(0.f, 0.f, 0.f, 0.f);
        if (gy >= 0 && gy < HH && gx >= 0 && gx < WW)
            vv = __ldg((const float4*)(vg + ((size_t)(gy*WW + gx))*32) + c8);
        *(float4*)(vs + pix*VSTRIDE + c8*4) = vv;
    }
    for (int idx = tid; idx < 288; idx += 256)
        ws9[idx] = g_lw[head*288 + idx];
    if (tid < 32)
        bsm[tid] = g_lb[head*32 + tid];
    else if (tid < 48)
        bias_sm[tid - 32] = g_bias[head*16 + (tid - 32)];
    __syncthreads();

    const int w  = tid >> 2;
    const int i  = tid & 3;
    const int wy = w >> 3, wx = w & 7;
    const int sy = i >> 1, sx = i & 1;
    const int iy = wy*2 + sy, ix = wx*2 + sx;
    const int gy = y0 + iy,  gx = x0 + ix;

    const float* qg = g_q + ((size_t)nh * NPIX + (size_t)gy*WW + gx) * 32;
    float qr[32];
    #pragma unroll
    for (int c8 = 0; c8 < 8; ++c8) {
        float4 qv = __ldg((const float4*)qg + c8);
        qr[c8*4+0] = qv.x; qr[c8*4+1] = qv.y; qr[c8*4+2] = qv.z; qr[c8*4+3] = qv.w;
    }
    const float* kgbase = g_k + ((size_t)nh * NPIX + (size_t)(y0 + wy*2)*WW + (x0 + wx*2)) * 32;
    float lg[4];
    #pragma unroll
    for (int j = 0; j < 4; ++j) {
        const float* kg = kgbase + ((size_t)((j >> 1)*WW + (j & 1))) * 32;
        float s = 0.f;
        #pragma unroll
        for (int c8 = 0; c8 < 8; ++c8) {
            float4 kv = __ldg((const float4*)kg + c8);
            s = fmaf(qr[c8*4+0], kv.x, s);
            s = fmaf(qr[c8*4+1], kv.y, s);
            s = fmaf(qr[c8*4+2], kv.z, s);
            s = fmaf(qr[c8*4+3], kv.w, s);
        }
        lg[j] = s;
    }
    const float scale = 0.17677669529663687f;
    #pragma unroll
    for (int j = 0; j < 4; ++j) lg[j] = lg[j]*scale + bias_sm[i*4 + j];

    float m  = fmaxf(fmaxf(lg[0], lg[1]), fmaxf(lg[2], lg[3]));
    float a0 = expf(lg[0] - m);
    float a1 = expf(lg[1] - m);
    float a2 = expf(lg[2] - m);
    float a3 = expf(lg[3] - m);
    float inv = 1.0f / (a0 + a1 + a2 + a3);
    a0 *= inv; a1 *= inv; a2 *= inv; a3 *= inv;

    int vj0 = ((wy*2 + 1)*18 + (wx*2 + 1)) * VSTRIDE;
    int vj1 = ((wy*2 + 1)*18 + (wx*2 + 2)) * VSTRIDE;
    int vj2 = ((wy*2 + 2)*18 + (wx*2 + 1)) * VSTRIDE;
    int vj3 = ((wy*2 + 2)*18 + (wx*2 + 2)) * VSTRIDE;

    const size_t ob = ((size_t)(b*256 + half*128 + head)) * NPIX + (size_t)gy*WW + gx;

    #pragma unroll
    for (int c8 = 0; c8 < 8; ++c8) {
        float4 v0 = *(const float4*)(vs + vj0 + c8*4);
        float4 v1 = *(const float4*)(vs + vj1 + c8*4);
        float4 v2 = *(const float4*)(vs + vj2 + c8*4);
        float4 v3 = *(const float4*)(vs + vj3 + c8*4);

        float ox = a0*v0.x; ox = fmaf(a1, v1.x, ox); ox = fmaf(a2, v2.x, ox); ox = fmaf(a3, v3.x, ox);
        float oy = a0*v0.y; oy = fmaf(a1, v1.y, oy); oy = fmaf(a2, v2.y, oy); oy = fmaf(a3, v3.y, oy);
        float oz = a0*v0.z; oz = fmaf(a1, v1.z, oz); oz = fmaf(a2, v2.z, oz); oz = fmaf(a3, v3.z, oz);
        float ow = a0*v0.w; ow = fmaf(a1, v1.w, ow); ow = fmaf(a2, v2.w, ow); ow = fmaf(a3, v3.w, ow);

        #pragma unroll
        for (int t = 0; t < 9; ++t) {
            int dy = t / 3, dx = t - dy*3;
            float4 vv = *(const float4*)(vs + ((iy + dy)*18 + (ix + dx))*VSTRIDE + c8*4);
            float4 wv = *(const float4*)(ws9 + t*32 + c8*4);
            ox = fmaf(wv.x, vv.x, ox);
            oy = fmaf(wv.y, vv.y, oy);
            oz = fmaf(wv.z, vv.z, oz);
            ow = fmaf(wv.w, vv.w, ow);
        }
        float4 bb = *(const float4*)(bsm + c8*4);
        ox += bb.x; oy += bb.y; oz += bb.z; ow += bb.w;

        out[ob + (size_t)(c8*4 + 0) * 4 * NPIX] = ox;
        out[ob + (size_t)(c8*4 + 1) * 4 * NPIX] = oy;
        out[ob + (size_t)(c8*4 + 2) * 4 * NPIX] = oz;
        out[ob + (size_t)(c8*4 + 3) * 4 * NPIX] = ow;
    }
}

// ---------------------------------------------------------------------------
// Launcher
// ---------------------------------------------------------------------------
extern "C" void kernel_launch(void* const* d_in, const int* in_sizes, int n_in,
                              void* d_out, int out_size)
{
    const float* x          = (const float*)d_in[0];
    const float* qkv_w      = (const float*)d_in[1];
    const float* lepe_w     = (const float*)d_in[2];
    const float* lepe_b     = (const float*)d_in[3];
    const float* bias_table = (const float*)d_in[4];
    const int*   rel_idx    = (const int*)  d_in[5];
    float* out = (float*)d_out;

    cudaFuncSetAttribute(qkv_hmma_kernel, cudaFuncAttributeMaxDynamicSharedMemorySize, SM_TOT);

    prep_kernel<<<1, 256>>>(lepe_w, lepe_b, bias_table, rel_idx);

    dim3 g1(NPIX/128, NB);           // 288 x 8
    qkv_hmma_kernel<<<g1, 256, SM_TOT>>>(x, qkv_w);

    dim3 g2(WW/16, HH/16, NB*NHEAD); // 12 x 12 x 32
    attn_kernel<<<g2, 256>>>(out);
}

// round 5
// speedup vs baseline: 1.3215x; 1.1128x over previous
#include <cuda_runtime.h>
#include <cuda_bf16.h>
#include <cstdint>

// ---------------------------------------------------------------------------
// Problem constants
// ---------------------------------------------------------------------------
#define HH    192
#define WW    192
#define NPIX  (HH*WW)          // 36864
#define NB    8                // 2 halves * batch 4
#define NHEAD 4

// ---------------------------------------------------------------------------
// Device scratch
// q/k/v layout: [n(8)][head(4)][pixel(36864)][hd(32)]
// ---------------------------------------------------------------------------
__device__ float g_q[8*4*NPIX*32];
__device__ float g_k[8*4*NPIX*32];
__device__ float g_v[8*4*NPIX*32];
__device__ float g_lw[4*9*32];      // [head][tap][hd] lepe weights
__device__ float g_lb[4*32];        // [head][hd] lepe bias
__device__ float g_bias[4*16];      // [head][i*4+j] attention bias

// ---------------------------------------------------------------------------
// tf32 helpers (base-ISA mma.sync)
// ---------------------------------------------------------------------------
__device__ __forceinline__ uint32_t cvt_tf32(float v) {
    uint32_t t;
    asm("cvt.rna.tf32.f32 %0, %1;" : "=r"(t) : "f"(v));
    return t;
}
__device__ __forceinline__ void mma_tf32(float* c, const uint4& a, const uint2& b) {
    asm volatile(
        "mma.sync.aligned.m16n8k8.row.col.f32.tf32.tf32.f32 "
        "{%0,%1,%2,%3}, {%4,%5,%6,%7}, {%8,%9}, {%0,%1,%2,%3};"
        : "+f"(c[0]), "+f"(c[1]), "+f"(c[2]), "+f"(c[3])
        : "r"(a.x), "r"(a.y), "r"(a.z), "r"(a.w), "r"(b.x), "r"(b.y));
}

// smem layout (floats):
//   A frag @ 0      : 16384 floats (128 pix x 128 k, fragment-major + XOR swizzle)
//   B buf  @ 16384  : 16 ksteps x (16 ntiles x 64 + 2 pad) = 16416 floats
//   C buf  @ 32800  : 4 heads x 128 pix x 36 = 18432 floats (epilogue staging)
#define B_KSTRIDE 1026
#define SMF_B  16384
#define SMF_C  (16384 + 16*B_KSTRIDE)            // 32800
#define SM_TOT ((SMF_C + 4*128*36) * 4)          // 204928 bytes

// ---------------------------------------------------------------------------
// Kernel 0: lepe / bias re-layout (tiny)
// ---------------------------------------------------------------------------
__global__ void prep_kernel(const float* __restrict__ lepe_w,
                            const float* __restrict__ lepe_b,
                            const float* __restrict__ bias_table,
                            const int*   __restrict__ rel_idx)
{
    int t = threadIdx.x;
    for (int idx = t; idx < 4*9*32; idx += 256) {
        int head = idx / 288;
        int r    = idx % 288;
        int tap  = r >> 5;
        int hd   = r & 31;
        g_lw[idx] = lepe_w[(hd*4 + head)*9 + tap];
    }
    if (t < 128) {
        int head = t >> 5, hd = t & 31;
        g_lb[t] = lepe_b[hd*4 + head];
    }
    if (t < 64) {
        int head = t >> 4, ij = t & 15;
        g_bias[t] = bias_table[rel_idx[ij]*4 + head];
    }
}

// ---------------------------------------------------------------------------
// B staging: weights [o(128)][k(128)] fp32 -> tf32 fragment-major
// ---------------------------------------------------------------------------
__device__ __forceinline__ void stage_b_frag(uint32_t* __restrict__ Bs,
                                             const float* __restrict__ w, int tid)
{
    #pragma unroll
    for (int it = 0; it < 16; ++it) {
        int i  = it*256 + tid;
        int o  = i >> 5;          // output channel (n)
        int k4 = i & 31;          // float4 index along k
        float4 v = __ldg((const float4*)(w + (size_t)o*128) + k4);
        int kstep = k4 >> 1, r = k4 & 1;
        uint32_t base = (uint32_t)(kstep*B_KSTRIDE + (o>>3)*64 + (o&7)*8 + r);
        Bs[base + 0] = cvt_tf32(v.x);
        Bs[base + 2] = cvt_tf32(v.y);
        Bs[base + 4] = cvt_tf32(v.z);
        Bs[base + 6] = cvt_tf32(v.w);
    }
}

// ---------------------------------------------------------------------------
// MMA mainloop: 16 ksteps of m16n8k8 tf32; warp tile 32(M) x 64(N)
// ---------------------------------------------------------------------------
__device__ __forceinline__ void do_mma(float acc[2][8][4],
                                       const uint32_t* __restrict__ As,
                                       const uint32_t* __restrict__ Bs,
                                       int warp_m, int warp_n, int lane)
{
    #pragma unroll
    for (int i = 0; i < 2; ++i)
        #pragma unroll
        for (int j = 0; j < 8; ++j)
            #pragma unroll
            for (int e = 0; e < 4; ++e) acc[i][j][e] = 0.0f;

    #pragma unroll
    for (int kstep = 0; kstep < 16; ++kstep) {
        uint4 a[2];
        #pragma unroll
        for (int i = 0; i < 2; ++i) {
            uint32_t u = (uint32_t)((kstep*8 + warp_m*2 + i)*32 + lane);
            u ^= (u >> 3) & 7;
            a[i] = *(const uint4*)(As + (size_t)u*4);
        }
        uint2 bf[8];
        #pragma unroll
        for (int j = 0; j < 8; ++j)
            bf[j] = *(const uint2*)(Bs + kstep*B_KSTRIDE + (warp_n*8 + j)*64 + lane*2);

        #pragma unroll
        for (int i = 0; i < 2; ++i)
            #pragma unroll
            for (int j = 0; j < 8; ++j)
                mma_tf32(acc[i][j], a[i], bf[j]);
    }
}

// ---------------------------------------------------------------------------
// acc -> Cs[h][pix][36-pad]  (head-split, pixel-major; conflict-light STS)
// ---------------------------------------------------------------------------
__device__ __forceinline__ void write_c(const float acc[2][8][4],
                                        float* __restrict__ Cs,
                                        int warp_m, int warp_n, int lane)
{
    const int g  = lane >> 2;
    const int tg = lane & 3;
    #pragma unroll
    for (int i = 0; i < 2; ++i) {
        int pl = warp_m*32 + i*16 + g;
        #pragma unroll
        for (int j = 0; j < 8; ++j) {
            int o0 = warp_n*64 + j*8 + 2*tg;
            int h0 = o0 & 3, h1 = (o0 + 1) & 3;
            int hd = o0 >> 2;
            Cs[(h0*128 + pl    )*36 + hd] = acc[i][j][0];
            Cs[(h1*128 + pl    )*36 + hd] = acc[i][j][1];
            Cs[(h0*128 + pl + 8)*36 + hd] = acc[i][j][2];
            Cs[(h1*128 + pl + 8)*36 + hd] = acc[i][j][3];
        }
    }
}

// ---------------------------------------------------------------------------
// Cs -> dst: fully coalesced 128B-per-(head,pixel) linear stores
// ---------------------------------------------------------------------------
__device__ __forceinline__ void drain_c(const float* __restrict__ Cs,
                                        float* __restrict__ dst,
                                        int tid, int p0, size_t n4)
{
    #pragma unroll
    for (int rr = 0; rr < 2; ++rr) {
        int r   = tid + rr*256;
        int h   = r >> 7;
        int pix = r & 127;
        const float4* src = (const float4*)(Cs + (size_t)(h*128 + pix)*36);
        float4* d = (float4*)(dst + ((n4 + h)*NPIX + (size_t)(p0 + pix))*32);
        #pragma unroll
        for (int c = 0; c < 8; ++c) d[c] = src[c];
    }
}

// ---------------------------------------------------------------------------
// Kernel 1: QKV 1x1 conv as tf32 mma.sync GEMM, coalesced epilogue.
// CTA: 256 threads (8 warps, 4M x 2N), M=128 pixels, K=128, 3 passes of N=128.
// ---------------------------------------------------------------------------
__global__ void __launch_bounds__(256)
qkv_hmma_kernel(const float* __restrict__ x, const float* __restrict__ qkv_w)
{
    extern __shared__ __align__(16) float smf[];
    uint32_t* As = (uint32_t*)smf;
    uint32_t* Bs = (uint32_t*)(smf + SMF_B);
    float*    Cs = smf + SMF_C;

    const int tid    = threadIdx.x;
    const int lane   = tid & 31;
    const int wid    = tid >> 5;
    const int warp_m = wid >> 1;    // 0..3
    const int warp_n = wid & 1;     // 0..1
    const int n      = blockIdx.y;
    const int half   = n >> 2;
    const int b      = n & 3;
    const int p0     = blockIdx.x * 128;
    const size_t n4  = (size_t)n * 4;

    // ---- stage A: x (planar [ch][pix]) -> tf32 fragment-major + swizzle ----
    {
        const int pix = tid & 127;
        const int kh  = tid >> 7;                     // k-half 0..1
        const float* xb = x + ((size_t)(b*256 + half*128 + kh*64)) * NPIX + p0 + pix;
        const int mtile   = pix >> 4;
        const int g       = pix & 7;
        const int rowhalf = (pix >> 3) & 1;
        #pragma unroll 8
        for (int k2 = 0; k2 < 64; ++k2) {
            int k = kh*64 + k2;
            float v = __ldg(xb + (size_t)k2 * NPIX);
            int kstep = k >> 3, tg = k & 3, colhalf = (k >> 2) & 1;
            uint32_t u = (uint32_t)((kstep*8 + mtile)*32 + g*4 + tg);
            u ^= (u >> 3) & 7;
            As[u*4 + colhalf*2 + rowhalf] = cvt_tf32(v);
        }
    }
    stage_b_frag(Bs, qkv_w, tid);                 // q weights
    __syncthreads();

    float acc[2][8][4];

    // ---- pass 0 (q) ----
    do_mma(acc, As, Bs, warp_m, warp_n, lane);
    __syncthreads();                               // all warps done reading Bs
    write_c(acc, Cs, warp_m, warp_n, lane);
    stage_b_frag(Bs, qkv_w + 16384, tid);          // k weights
    __syncthreads();

    // ---- pass 1 (k): drain q while MMAs run ----
    drain_c(Cs, g_q, tid, p0, n4);
    do_mma(acc, As, Bs, warp_m, warp_n, lane);
    __syncthreads();                               // drain done + Bs free
    write_c(acc, Cs, warp_m, warp_n, lane);
    stage_b_frag(Bs, qkv_w + 32768, tid);          // v weights
    __syncthreads();

    // ---- pass 2 (v): drain k while MMAs run ----
    drain_c(Cs, g_k, tid, p0, n4);
    do_mma(acc, As, Bs, warp_m, warp_n, lane);
    __syncthreads();
    write_c(acc, Cs, warp_m, warp_n, lane);
    __syncthreads();
    drain_c(Cs, g_v, tid, p0, n4);
}

// ---------------------------------------------------------------------------
// Kernel 2: window attention + LePE + output scatter (unchanged, passing)
// ---------------------------------------------------------------------------
#define VSTRIDE 36

__global__ void __launch_bounds__(256)
attn_kernel(float* __restrict__ out)
{
    __shared__ __align__(16) float vs[324 * VSTRIDE];   // 18x18 halo tile
    __shared__ __align__(16) float ws9[9 * 32];
    __shared__ __align__(16) float bsm[32];
    __shared__ __align__(16) float bias_sm[16];

    const int nh   = blockIdx.z;
    const int n    = nh >> 2;
    const int head = nh & 3;
    const int half = n >> 2;
    const int b    = n & 3;
    const int y0   = blockIdx.y * 16;
    const int x0   = blockIdx.x * 16;
    const int tid  = threadIdx.x;

    const float* vg = g_v + (size_t)nh * NPIX * 32;

    for (int idx = tid; idx < 324*8; idx += 256) {
        int pix = idx >> 3;
        int c8  = idx & 7;
        int ly  = pix / 18;
        int lx  = pix - ly*18;
        int gy  = y0 + ly - 1;
        int gx  = x0 + lx - 1;
        float4 vv = make_float4(0.f, 0.f, 0.f, 0.f);
        if (gy >= 0 && gy < HH && gx >= 0 && gx < WW)
            vv = __ldg((const float4*)(vg + ((size_t)(gy*WW + gx))*32) + c8);
        *(float4*)(vs + pix*VSTRIDE + c8*4) = vv;
    }
    for (int idx = tid; idx < 288; idx += 256)
        ws9[idx] = g_lw[head*288 + idx];
    if (tid < 32)
        bsm[tid] = g_lb[head*32 + tid];
    else if (tid < 48)
        bias_sm[tid - 32] = g_bias[head*16 + (tid - 32)];
    __syncthreads();

    const int w  = tid >> 2;
    const int i  = tid & 3;
    const int wy = w >> 3, wx = w & 7;
    const int sy = i >> 1, sx = i & 1;
    const int iy = wy*2 + sy, ix = wx*2 + sx;
    const int gy = y0 + iy,  gx = x0 + ix;

    const float* qg = g_q + ((size_t)nh * NPIX + (size_t)gy*WW + gx) * 32;
    float qr[32];
    #pragma unroll
    for (int c8 = 0; c8 < 8; ++c8) {
        float4 qv = __ldg((const float4*)qg + c8);
        qr[c8*4+0] = qv.x; qr[c8*4+1] = qv.y; qr[c8*4+2] = qv.z; qr[c8*4+3] = qv.w;
    }
    const float* kgbase = g_k + ((size_t)nh * NPIX + (size_t)(y0 + wy*2)*WW + (x0 + wx*2)) * 32;
    float lg[4];
    #pragma unroll
    for (int j = 0; j < 4; ++j) {
        const float* kg = kgbase + ((size_t)((j >> 1)*WW + (j & 1))) * 32;
        float s = 0.f;
        #pragma unroll
        for (int c8 = 0; c8 < 8; ++c8) {
            float4 kv = __ldg((const float4*)kg + c8);
            s = fmaf(qr[c8*4+0], kv.x, s);
            s = fmaf(qr[c8*4+1], kv.y, s);
            s = fmaf(qr[c8*4+2], kv.z, s);
            s = fmaf(qr[c8*4+3], kv.w, s);
        }
        lg[j] = s;
    }
    const float scale = 0.17677669529663687f;
    #pragma unroll
    for (int j = 0; j < 4; ++j) lg[j] = lg[j]*scale + bias_sm[i*4 + j];

    float m  = fmaxf(fmaxf(lg[0], lg[1]), fmaxf(lg[2], lg[3]));
    float a0 = expf(lg[0] - m);
    float a1 = expf(lg[1] - m);
    float a2 = expf(lg[2] - m);
    float a3 = expf(lg[3] - m);
    float inv = 1.0f / (a0 + a1 + a2 + a3);
    a0 *= inv; a1 *= inv; a2 *= inv; a3 *= inv;

    int vj0 = ((wy*2 + 1)*18 + (wx*2 + 1)) * VSTRIDE;
    int vj1 = ((wy*2 + 1)*18 + (wx*2 + 2)) * VSTRIDE;
    int vj2 = ((wy*2 + 2)*18 + (wx*2 + 1)) * VSTRIDE;
    int vj3 = ((wy*2 + 2)*18 + (wx*2 + 2)) * VSTRIDE;

    const size_t ob = ((size_t)(b*256 + half*128 + head)) * NPIX + (size_t)gy*WW + gx;

    #pragma unroll
    for (int c8 = 0; c8 < 8; ++c8) {
        float4 v0 = *(const float4*)(vs + vj0 + c8*4);
        float4 v1 = *(const float4*)(vs + vj1 + c8*4);
        float4 v2 = *(const float4*)(vs + vj2 + c8*4);
        float4 v3 = *(const float4*)(vs + vj3 + c8*4);

        float ox = a0*v0.x; ox = fmaf(a1, v1.x, ox); ox = fmaf(a2, v2.x, ox); ox = fmaf(a3, v3.x, ox);
        float oy = a0*v0.y; oy = fmaf(a1, v1.y, oy); oy = fmaf(a2, v2.y, oy); oy = fmaf(a3, v3.y, oy);
        float oz = a0*v0.z; oz = fmaf(a1, v1.z, oz); oz = fmaf(a2, v2.z, oz); oz = fmaf(a3, v3.z, oz);
        float ow = a0*v0.w; ow = fmaf(a1, v1.w, ow); ow = fmaf(a2, v2.w, ow); ow = fmaf(a3, v3.w, ow);

        #pragma unroll
        for (int t = 0; t < 9; ++t) {
            int dy = t / 3, dx = t - dy*3;
            float4 vv = *(const float4*)(vs + ((iy + dy)*18 + (ix + dx))*VSTRIDE + c8*4);
            float4 wv = *(const float4*)(ws9 + t*32 + c8*4);
            ox = fmaf(wv.x, vv.x, ox);
            oy = fmaf(wv.y, vv.y, oy);
            oz = fmaf(wv.z, vv.z, oz);
            ow = fmaf(wv.w, vv.w, ow);
        }
        float4 bb = *(const float4*)(bsm + c8*4);
        ox += bb.x; oy += bb.y; oz += bb.z; ow += bb.w;

        out[ob + (size_t)(c8*4 + 0) * 4 * NPIX] = ox;
        out[ob + (size_t)(c8*4 + 1) * 4 * NPIX] = oy;
        out[ob + (size_t)(c8*4 + 2) * 4 * NPIX] = oz;
        out[ob + (size_t)(c8*4 + 3) * 4 * NPIX] = ow;
    }
}

// ---------------------------------------------------------------------------
// Launcher
// ---------------------------------------------------------------------------
extern "C" void kernel_launch(void* const* d_in, const int* in_sizes, int n_in,
                              void* d_out, int out_size)
{
    const float* x          = (const float*)d_in[0];
    const float* qkv_w      = (const float*)d_in[1];
    const float* lepe_w     = (const float*)d_in[2];
    const float* lepe_b     = (const float*)d_in[3];
    const float* bias_table = (const float*)d_in[4];
    const int*   rel_idx    = (const int*)  d_in[5];
    float* out = (float*)d_out;

    cudaFuncSetAttribute(qkv_hmma_kernel, cudaFuncAttributeMaxDynamicSharedMemorySize, SM_TOT);

    prep_kernel<<<1, 256>>>(lepe_w, lepe_b, bias_table, rel_idx);

    dim3 g1(NPIX/128, NB);           // 288 x 8
    qkv_hmma_kernel<<<g1, 256, SM_TOT>>>(x, qkv_w);

    dim3 g2(WW/16, HH/16, NB*NHEAD); // 12 x 12 x 32
    attn_kernel<<<g2, 256>>>(out);
}

// round 6
// speedup vs baseline: 1.4847x; 1.1235x over previous
#include <cuda_runtime.h>
#include <cuda_bf16.h>
#include <cstdint>

// ---------------------------------------------------------------------------
// Problem constants
// ---------------------------------------------------------------------------
#define HH    192
#define WW    192
#define NPIX  (HH*WW)          // 36864
#define NB    8                // 2 halves * batch 4
#define NHEAD 4

// ---------------------------------------------------------------------------
// Device scratch: only v round-trips now.
// v layout: [n(8)][head(4)][pixel(36864)][hd(32)]
// ---------------------------------------------------------------------------
__device__ float g_v[8*4*NPIX*32];
__device__ float g_lw[4*9*32];      // [head][tap][hd] lepe weights
__device__ float g_lb[4*32];        // [head][hd] lepe bias
__device__ float g_bias[4*16];      // [head][i*4+j] attention bias

// ---------------------------------------------------------------------------
// tf32 helpers (base-ISA mma.sync)
// ---------------------------------------------------------------------------
__device__ __forceinline__ uint32_t cvt_tf32(float v) {
    uint32_t t;
    asm("cvt.rna.tf32.f32 %0, %1;" : "=r"(t) : "f"(v));
    return t;
}
__device__ __forceinline__ void mma_tf32(float* c, const uint4& a, const uint2& b) {
    asm volatile(
        "mma.sync.aligned.m16n8k8.row.col.f32.tf32.tf32.f32 "
        "{%0,%1,%2,%3}, {%4,%5,%6,%7}, {%8,%9}, {%0,%1,%2,%3};"
        : "+f"(c[0]), "+f"(c[1]), "+f"(c[2]), "+f"(c[3])
        : "r"(a.x), "r"(a.y), "r"(a.z), "r"(a.w), "r"(b.x), "r"(b.y));
}

#define B_KSTRIDE 1026

// ---- K_fused smem map (floats) --------------------------------------------
// [0 .. 16384)        A tile (128 pix x 128 k, fragment-major + swizzle)
// [16384 .. 20488)    B chunk 0 (4 ksteps)
// [20488 .. 24592)    B chunk 1
//   (A+B region is overlaid by vs[2][264][36] = 19008 floats during attention)
// [24592 .. 43024)    Ks: k results, 4 heads x 128 pix x 36
// [43024 .. 52240)    Qs: q results, 2 heads x 128 pix x 36 (one pair)
// [52240 .. 53392)    lepe weights (4 x 9 x 32)
// [53392 .. 53520)    lepe bias (4 x 32)
// [53520 .. 53584)    attn bias (4 x 16)
#define SMF_B0   16384
#define SMF_B1   20488
#define SMF_K    24592
#define SMF_Q    43024
#define SMF_LW   52240
#define SMF_LB   53392
#define SMF_BIAS 53520
#define SM_TOT_F (53584*4)     // 214336 B

// ---- K_v smem map (floats) -------------------------------------------------
// [0..16384) A   [16384..32800) B full (16 ksteps)   [32800..51232) Cs
#define SMF_VB  16384
#define SMF_VC  32800
#define SM_TOT_V (51232*4)     // 204928 B

// ---------------------------------------------------------------------------
// Kernel 0: lepe / bias re-layout (tiny)
// ---------------------------------------------------------------------------
__global__ void prep_kernel(const float* __restrict__ lepe_w,
                            const float* __restrict__ lepe_b,
                            const float* __restrict__ bias_table,
                            const int*   __restrict__ rel_idx)
{
    int t = threadIdx.x;
    for (int idx = t; idx < 4*9*32; idx += 256) {
        int head = idx / 288;
        int r    = idx % 288;
        int tap  = r >> 5;
        int hd   = r & 31;
        g_lw[idx] = lepe_w[(hd*4 + head)*9 + tap];
    }
    if (t < 128) {
        int head = t >> 5, hd = t & 31;
        g_lb[t] = lepe_b[hd*4 + head];
    }
    if (t < 64) {
        int head = t >> 4, ij = t & 15;
        g_bias[t] = bias_table[rel_idx[ij]*4 + head];
    }
}

// ---------------------------------------------------------------------------
// B chunk staging: weights [o(128)][k(128)] -> tf32 fragment-major, 4 ksteps
// ---------------------------------------------------------------------------
__device__ __forceinline__ void stage_b_chunk(uint32_t* __restrict__ Bc,
                                              const float* __restrict__ w,
                                              int c, int tid)
{
    #pragma unroll
    for (int it = 0; it < 2; ++it) {
        int i   = it*512 + tid;      // 0..1023
        int o   = i >> 3;            // 0..127
        int k4l = i & 7;
        float4 v = __ldg((const float4*)(w + (size_t)o*128) + (c*8 + k4l));
        int l = k4l >> 1, r = k4l & 1;
        uint32_t base = (uint32_t)(l*B_KSTRIDE + (o>>3)*64 + (o&7)*8 + r);
        Bc[base + 0] = cvt_tf32(v.x);
        Bc[base + 2] = cvt_tf32(v.y);
        Bc[base + 4] = cvt_tf32(v.z);
        Bc[base + 6] = cvt_tf32(v.w);
    }
}

// ---------------------------------------------------------------------------
// MMA over one 4-kstep chunk; 16 warps: warp tile 32(M) x 32(N)
// ---------------------------------------------------------------------------
__device__ __forceinline__ void mma_chunk4(float acc[2][4][4],
                                           const uint32_t* __restrict__ As,
                                           const uint32_t* __restrict__ Bc,
                                           int ks0, int warp_m, int warp_n, int lane)
{
    #pragma unroll
    for (int l = 0; l < 4; ++l) {
        const int kg = ks0 + l;
        uint4 a[2];
        #pragma unroll
        for (int i = 0; i < 2; ++i) {
            uint32_t u = (uint32_t)((kg*8 + warp_m*2 + i)*32 + lane);
            u ^= (u >> 3) & 7;
            a[i] = *(const uint4*)(As + (size_t)u*4);
        }
        uint2 bf[4];
        #pragma unroll
        for (int j = 0; j < 4; ++j)
            bf[j] = *(const uint2*)(Bc + l*B_KSTRIDE + (warp_n*4 + j)*64 + lane*2);
        #pragma unroll
        for (int i = 0; i < 2; ++i)
            #pragma unroll
            for (int j = 0; j < 4; ++j)
                mma_tf32(acc[i][j], a[i], bf[j]);
    }
}

__device__ __forceinline__ void acc_zero(float acc[2][4][4]) {
    #pragma unroll
    for (int i = 0; i < 2; ++i)
        #pragma unroll
        for (int j = 0; j < 4; ++j)
            #pragma unroll
            for (int e = 0; e < 4; ++e) acc[i][j][e] = 0.0f;
}

// acc -> Cs[head(4)][pix 128][36]
__device__ __forceinline__ void write_c_all(const float acc[2][4][4],
                                            float* __restrict__ Cs,
                                            int warp_m, int warp_n, int lane)
{
    const int g  = lane >> 2;
    const int tg = lane & 3;
    #pragma unroll
    for (int i = 0; i < 2; ++i) {
        int pl = warp_m*32 + i*16 + g;
        #pragma unroll
        for (int j = 0; j < 4; ++j) {
            int o0 = warp_n*32 + j*8 + 2*tg;
            int h0 = o0 & 3, h1 = (o0 + 1) & 3;
            int hd = o0 >> 2;
            Cs[(h0*128 + pl    )*36 + hd] = acc[i][j][0];
            Cs[(h1*128 + pl    )*36 + hd] = acc[i][j][1];
            Cs[(h0*128 + pl + 8)*36 + hd] = acc[i][j][2];
            Cs[(h1*128 + pl + 8)*36 + hd] = acc[i][j][3];
        }
    }
}

// acc -> Qs[hh(2)][pix 128][36] for one head-pair (pair 0: heads 0,1; pair 1: 2,3)
__device__ __forceinline__ void write_c_pair(const float acc[2][4][4],
                                             float* __restrict__ Qs, int pair,
                                             int warp_m, int warp_n, int lane)
{
    const int g  = lane >> 2;
    const int tg = lane & 3;
    if ((tg & 1) != pair) return;
    #pragma unroll
    for (int i = 0; i < 2; ++i) {
        int pl = warp_m*32 + i*16 + g;
        #pragma unroll
        for (int j = 0; j < 4; ++j) {
            int o0 = warp_n*32 + j*8 + 2*tg;
            int hd = o0 >> 2;
            Qs[(0*128 + pl    )*36 + hd] = acc[i][j][0];
            Qs[(1*128 + pl    )*36 + hd] = acc[i][j][1];
            Qs[(0*128 + pl + 8)*36 + hd] = acc[i][j][2];
            Qs[(1*128 + pl + 8)*36 + hd] = acc[i][j][3];
        }
    }
}

// ---------------------------------------------------------------------------
// Kernel 1: v = 1x1 conv (tf32 GEMM), linear 128-pixel blocks, coalesced drain
// ---------------------------------------------------------------------------
__global__ void __launch_bounds__(512)
v_kernel(const float* __restrict__ x, const float* __restrict__ qkv_w)
{
    extern __shared__ __align__(16) float smf[];
    uint32_t* As = (uint32_t*)smf;
    uint32_t* Bf = (uint32_t*)(smf + SMF_VB);
    float*    Cs = smf + SMF_VC;

    const int tid    = threadIdx.x;
    const int lane   = tid & 31;
    const int wid    = tid >> 5;
    const int warp_m = wid >> 2;    // 0..3
    const int warp_n = wid & 3;     // 0..3
    const int n      = blockIdx.y;
    const int half   = n >> 2;
    const int b      = n & 3;
    const int p0     = blockIdx.x * 128;
    const size_t n4  = (size_t)n * 4;

    // stage A (linear pixel block)
    {
        const int pix = tid & 127;
        const int kh  = tid >> 7;    // 0..3
        const float* xb = x + ((size_t)(b*256 + half*128 + kh*32)) * NPIX + p0 + pix;
        const int mtile   = pix >> 4;
        const int g       = pix & 7;
        const int rowhalf = (pix >> 3) & 1;
        #pragma unroll 8
        for (int k2 = 0; k2 < 32; ++k2) {
            int k = kh*32 + k2;
            float v = __ldg(xb + (size_t)k2 * NPIX);
            int kstep = k >> 3, tg = k & 3, colhalf = (k >> 2) & 1;
            uint32_t u = (uint32_t)((kstep*8 + mtile)*32 + g*4 + tg);
            u ^= (u >> 3) & 7;
            As[u*4 + colhalf*2 + rowhalf] = cvt_tf32(v);
        }
    }
    // stage full B (v weights)
    {
        const float* w = qkv_w + 32768;
        #pragma unroll
        for (int it = 0; it < 8; ++it) {
            int i  = it*512 + tid;     // 0..4095
            int o  = i >> 5;
            int k4 = i & 31;
            float4 v = __ldg((const float4*)(w + (size_t)o*128) + k4);
            int kstep = k4 >> 1, r = k4 & 1;
            uint32_t base = (uint32_t)(kstep*B_KSTRIDE + (o>>3)*64 + (o&7)*8 + r);
            Bf[base + 0] = cvt_tf32(v.x);
            Bf[base + 2] = cvt_tf32(v.y);
            Bf[base + 4] = cvt_tf32(v.z);
            Bf[base + 6] = cvt_tf32(v.w);
        }
    }
    __syncthreads();

    float acc[2][4][4];
    acc_zero(acc);
    #pragma unroll
    for (int c = 0; c < 4; ++c)
        mma_chunk4(acc, As, Bf + c*4*B_KSTRIDE, c*4, warp_m, warp_n, lane);

    write_c_all(acc, Cs, warp_m, warp_n, lane);
    __syncthreads();

    // drain: one (head,pixel) row per thread, 8 x STG.128 linear
    {
        int h   = tid >> 7;
        int pix = tid & 127;
        const float4* src = (const float4*)(Cs + (size_t)(h*128 + pix)*36);
        float4* d = (float4*)(g_v + ((n4 + h)*NPIX + (size_t)(p0 + pix))*32);
        #pragma unroll
        for (int c = 0; c < 8; ++c) d[c] = src[c];
    }
}

// ---------------------------------------------------------------------------
// Kernel 2: fused q,k GEMM + window attention + LePE.
// CTA = (tile_x: 64 cols, tile_y: 2 rows, n). 512 threads, 16 warps.
// ---------------------------------------------------------------------------
__global__ void __launch_bounds__(512)
qkv_attn_kernel(const float* __restrict__ x, const float* __restrict__ qkv_w,
                float* __restrict__ out)
{
    extern __shared__ __align__(16) float smf[];
    uint32_t* As  = (uint32_t*)smf;
    uint32_t* Bc0 = (uint32_t*)(smf + SMF_B0);
    uint32_t* Bc1 = (uint32_t*)(smf + SMF_B1);
    float*    Ks  = smf + SMF_K;
    float*    Qs  = smf + SMF_Q;

    const int tid    = threadIdx.x;
    const int lane   = tid & 31;
    const int wid    = tid >> 5;
    const int warp_m = wid >> 2;    // 0..3
    const int warp_n = wid & 3;     // 0..3
    const int n      = blockIdx.z;
    const int half   = n >> 2;
    const int b      = n & 3;
    const int x0     = blockIdx.x * 64;
    const int y0     = blockIdx.y * 2;

    // stage per-head constants
    for (int idx = tid; idx < 1152; idx += 512) smf[SMF_LW + idx] = g_lw[idx];
    if (tid < 128)                    smf[SMF_LB + tid] = g_lb[tid];
    else if (tid < 192)               smf[SMF_BIAS + tid - 128] = g_bias[tid - 128];

    // stage A: interior 2x64 tile, fragment-major tf32 + swizzle
    {
        const int pix = tid & 127;                // lr*64 + lc
        const int kh  = tid >> 7;                 // 0..3
        const int gy  = y0 + (pix >> 6);
        const int gx  = x0 + (pix & 63);
        const float* xb = x + ((size_t)(b*256 + half*128 + kh*32)) * NPIX
                            + (size_t)gy*WW + gx;
        const int mtile   = pix >> 4;
        const int g       = pix & 7;
        const int rowhalf = (pix >> 3) & 1;
        #pragma unroll 8
        for (int k2 = 0; k2 < 32; ++k2) {
            int k = kh*32 + k2;
            float v = __ldg(xb + (size_t)k2 * NPIX);
            int kstep = k >> 3, tg = k & 3, colhalf = (k >> 2) & 1;
            uint32_t u = (uint32_t)((kstep*8 + mtile)*32 + g*4 + tg);
            u ^= (u >> 3) & 7;
            As[u*4 + colhalf*2 + rowhalf] = cvt_tf32(v);
        }
    }

    float acc[2][4][4];

    // ---- k pass (weights at +16384), B streamed in 4 chunks ----
    stage_b_chunk(Bc0, qkv_w + 16384, 0, tid);
    __syncthreads();
    acc_zero(acc);
    #pragma unroll
    for (int c = 0; c < 4; ++c) {
        uint32_t* cur = (c & 1) ? Bc1 : Bc0;
        uint32_t* nxt = (c & 1) ? Bc0 : Bc1;
        if (c < 3) stage_b_chunk(nxt, qkv_w + 16384, c + 1, tid);
        mma_chunk4(acc, As, cur, c*4, warp_m, warp_n, lane);
        __syncthreads();
    }
    write_c_all(acc, Ks, warp_m, warp_n, lane);

    // ---- q pass (weights at +0) ----
    stage_b_chunk(Bc0, qkv_w, 0, tid);
    __syncthreads();
    acc_zero(acc);
    #pragma unroll
    for (int c = 0; c < 4; ++c) {
        uint32_t* cur = (c & 1) ? Bc1 : Bc0;
        uint32_t* nxt = (c & 1) ? Bc0 : Bc1;
        if (c < 3) stage_b_chunk(nxt, qkv_w, c + 1, tid);
        mma_chunk4(acc, As, cur, c*4, warp_m, warp_n, lane);
        __syncthreads();
    }
    // after trailing sync: A and B regions are dead -> vs overlay allowed

    const float scale = 0.17677669529663687f;  // 1/sqrt(32)

    #pragma unroll 1
    for (int pair = 0; pair < 2; ++pair) {
        // park this pair's q
        write_c_pair(acc, Qs, pair, warp_m, warp_n, lane);

        // stage vs[hh(2)][4x66 halo][36] from g_v (overlaying A/B region)
        for (int idx = tid; idx < 2*264*8; idx += 512) {
            int hh  = idx / 2112;
            int rem = idx - hh*2112;
            int pix = rem >> 3;
            int c8  = rem & 7;
            int py  = pix / 66;
            int px  = pix - py*66;
            int gy  = y0 - 1 + py;
            int gx  = x0 - 1 + px;
            float4 vv = make_float4(0.f, 0.f, 0.f, 0.f);
            if (gy >= 0 && gy < HH && gx >= 0 && gx < WW)
                vv = __ldg((const float4*)(g_v +
                        ((size_t)(n*4 + pair*2 + hh)*NPIX + (size_t)gy*WW + gx)*32) + c8);
            *(float4*)(smf + (size_t)(hh*264 + pix)*36 + c8*4) = vv;
        }
        __syncthreads();

        // attention + lepe: 256 active threads = 2 heads x 32 windows x 4 tokens
        if (tid < 256) {
            const int hp   = tid >> 7;
            const int t    = tid & 127;
            const int w    = t >> 2;
            const int i    = t & 3;
            const int head = pair*2 + hp;
            const int sy   = i >> 1, sx = i & 1;
            const int lx   = 2*w + sx;
            const int gy   = y0 + sy, gx = x0 + lx;

            // q (32 ch) from Qs
            const float* qp = Qs + (size_t)(hp*128 + sy*64 + lx)*36;
            float qr[32];
            #pragma unroll
            for (int c8 = 0; c8 < 8; ++c8) {
                float4 qv = *(const float4*)(qp + c8*4);
                qr[c8*4+0] = qv.x; qr[c8*4+1] = qv.y;
                qr[c8*4+2] = qv.z; qr[c8*4+3] = qv.w;
            }
            // logits vs 4 window tokens (k from Ks)
            float lg[4];
            #pragma unroll
            for (int j = 0; j < 4; ++j) {
                const float* kp = Ks + (size_t)(head*128 + (j>>1)*64 + 2*w + (j&1))*36;
                float s = 0.f;
                #pragma unroll
                for (int c8 = 0; c8 < 8; ++c8) {
                    float4 kv = *(const float4*)(kp + c8*4);
                    s = fmaf(qr[c8*4+0], kv.x, s);
                    s = fmaf(qr[c8*4+1], kv.y, s);
                    s = fmaf(qr[c8*4+2], kv.z, s);
                    s = fmaf(qr[c8*4+3], kv.w, s);
                }
                lg[j] = s*scale + smf[SMF_BIAS + head*16 + i*4 + j];
            }
            float m  = fmaxf(fmaxf(lg[0], lg[1]), fmaxf(lg[2], lg[3]));
            float a0 = expf(lg[0] - m);
            float a1 = expf(lg[1] - m);
            float a2 = expf(lg[2] - m);
            float a3 = expf(lg[3] - m);
            float inv = 1.0f / (a0 + a1 + a2 + a3);
            a0 *= inv; a1 *= inv; a2 *= inv; a3 *= inv;

            const float* vsb = smf + (size_t)hp*264*36;
            const float* vj0 = vsb + (size_t)((1)*66 + 1 + 2*w    )*36;
            const float* vj1 = vsb + (size_t)((1)*66 + 1 + 2*w + 1)*36;
            const float* vj2 = vsb + (size_t)((2)*66 + 1 + 2*w    )*36;
            const float* vj3 = vsb + (size_t)((2)*66 + 1 + 2*w + 1)*36;
            const float* lwp = smf + SMF_LW + head*288;
            const float* lbp = smf + SMF_LB + head*32;

            const size_t ob = ((size_t)(b*256 + half*128 + head)) * NPIX
                            + (size_t)gy*WW + gx;
            #pragma unroll
            for (int c8 = 0; c8 < 8; ++c8) {
                float4 v0 = *(const float4*)(vj0 + c8*4);
                float4 v1 = *(const float4*)(vj1 + c8*4);
                float4 v2 = *(const float4*)(vj2 + c8*4);
                float4 v3 = *(const float4*)(vj3 + c8*4);

                float ox = a0*v0.x; ox = fmaf(a1, v1.x, ox); ox = fmaf(a2, v2.x, ox); ox = fmaf(a3, v3.x, ox);
                float oy = a0*v0.y; oy = fmaf(a1, v1.y, oy); oy = fmaf(a2, v2.y, oy); oy = fmaf(a3, v3.y, oy);
                float oz = a0*v0.z; oz = fmaf(a1, v1.z, oz); oz = fmaf(a2, v2.z, oz); oz = fmaf(a3, v3.z, oz);
                float ow = a0*v0.w; ow = fmaf(a1, v1.w, ow); ow = fmaf(a2, v2.w, ow); ow = fmaf(a3, v3.w, ow);

                // LePE 3x3 around (sy, lx); halo origin at (-1,-1)
                #pragma unroll
                for (int tp = 0; tp < 9; ++tp) {
                    int dy = tp / 3, dx = tp - dy*3;
                    float4 vv = *(const float4*)(vsb +
                        (size_t)((sy + dy)*66 + lx + dx)*36 + c8*4);
                    float4 wv = *(const float4*)(lwp + tp*32 + c8*4);
                    ox = fmaf(wv.x, vv.x, ox);
                    oy = fmaf(wv.y, vv.y, oy);
                    oz = fmaf(wv.z, vv.z, oz);
                    ow = fmaf(wv.w, vv.w, ow);
                }
                float4 bb = *(const float4*)(lbp + c8*4);
                ox += bb.x; oy += bb.y; oz += bb.z; ow += bb.w;

                out[ob + (size_t)(c8*4 + 0) * 4 * NPIX] = ox;
                out[ob + (size_t)(c8*4 + 1) * 4 * NPIX] = oy;
                out[ob + (size_t)(c8*4 + 2) * 4 * NPIX] = oz;
                out[ob + (size_t)(c8*4 + 3) * 4 * NPIX] = ow;
            }
        }
        __syncthreads();   // pair0 reads done before Qs/vs rewritten
    }
}

// ---------------------------------------------------------------------------
// Launcher
// ---------------------------------------------------------------------------
extern "C" void kernel_launch(void* const* d_in, const int* in_sizes, int n_in,
                              void* d_out, int out_size)
{
    const float* x          = (const float*)d_in[0];
    const float* qkv_w      = (const float*)d_in[1];
    const float* lepe_w     = (const float*)d_in[2];
    const float* lepe_b     = (const float*)d_in[3];
    const float* bias_table = (const float*)d_in[4];
    const int*   rel_idx    = (const int*)  d_in[5];
    float* out = (float*)d_out;

    cudaFuncSetAttribute(v_kernel, cudaFuncAttributeMaxDynamicSharedMemorySize, SM_TOT_V);
    cudaFuncSetAttribute(qkv_attn_kernel, cudaFuncAttributeMaxDynamicSharedMemorySize, SM_TOT_F);

    prep_kernel<<<1, 256>>>(lepe_w, lepe_b, bias_table, rel_idx);

    dim3 gv(NPIX/128, NB);           // 288 x 8
    v_kernel<<<gv, 512, SM_TOT_V>>>(x, qkv_w);

    dim3 gf(WW/64, HH/2, NB);        // 3 x 96 x 8
    qkv_attn_kernel<<<gf, 512, SM_TOT_F>>>(x, qkv_w, out);
}

// round 7
// speedup vs baseline: 1.5027x; 1.0121x over previous
#include <cuda_runtime.h>
#include <cuda_bf16.h>
#include <cstdint>

// ---------------------------------------------------------------------------
// Problem constants
// ---------------------------------------------------------------------------
#define HH    192
#define WW    192
#define NPIX  (HH*WW)          // 36864
#define NB    8                // 2 halves * batch 4
#define NHEAD 4

// ---------------------------------------------------------------------------
// Device scratch: only v round-trips.
// v layout: [n(8)][head(4)][pixel(36864)][hd(32)]
// ---------------------------------------------------------------------------
__device__ float g_v[8*4*NPIX*32];
__device__ float g_lw[4*9*32];      // [head][tap][hd] lepe weights
__device__ float g_lb[4*32];        // [head][hd] lepe bias
__device__ float g_bias[4*16];      // [head][i*4+j] attention bias

// ---------------------------------------------------------------------------
// tf32 helpers (base-ISA mma.sync)
// ---------------------------------------------------------------------------
__device__ __forceinline__ uint32_t cvt_tf32(float v) {
    uint32_t t;
    asm("cvt.rna.tf32.f32 %0, %1;" : "=r"(t) : "f"(v));
    return t;
}
__device__ __forceinline__ void mma_tf32(float* c, const uint4& a, const uint2& b) {
    asm volatile(
        "mma.sync.aligned.m16n8k8.row.col.f32.tf32.tf32.f32 "
        "{%0,%1,%2,%3}, {%4,%5,%6,%7}, {%8,%9}, {%0,%1,%2,%3};"
        : "+f"(c[0]), "+f"(c[1]), "+f"(c[2]), "+f"(c[3])
        : "r"(a.x), "r"(a.y), "r"(a.z), "r"(a.w), "r"(b.x), "r"(b.y));
}

#define B_KSTRIDE 1026

// ---- fused-kernel smem map (floats), M=64, 2 CTAs/SM ------------------------
// [0 .. 8192)       A tile (64 pix x 128 k, fragment-major + swizzle)
// [8192 .. 12296)   B chunk (4 ksteps)
//   (A+B region overlaid by vs[2][136][36] = 9792 floats during attention)
// [12296 .. 21512)  Ks: 4 heads x 64 pix x 36
// [21512 .. 26120)  Qs: 2 heads x 64 pix x 36
// [26120 .. 27272)  lepe weights
// [27272 .. 27400)  lepe bias
// [27400 .. 27464)  attn bias
#define SMF_B    8192
#define SMF_K    12296
#define SMF_Q    21512
#define SMF_LW   26120
#define SMF_LB   27272
#define SMF_BIAS 27400
#define SM_TOT_F (27464*4)     // 109856 B -> 2 CTAs/SM

// ---- v-kernel smem map (floats), M=64, 2 CTAs/SM ----------------------------
// [0..8192) A   [8192..12296) B chunk   [12296..21512) Cs (4 x 64 x 36)
#define SMF_VB  8192
#define SMF_VC  12296
#define SM_TOT_V (21512*4)     // 86048 B -> 2 CTAs/SM

// ---------------------------------------------------------------------------
// Kernel 0: lepe / bias re-layout (tiny)
// ---------------------------------------------------------------------------
__global__ void prep_kernel(const float* __restrict__ lepe_w,
                            const float* __restrict__ lepe_b,
                            const float* __restrict__ bias_table,
                            const int*   __restrict__ rel_idx)
{
    int t = threadIdx.x;
    for (int idx = t; idx < 4*9*32; idx += 256) {
        int head = idx / 288;
        int r    = idx % 288;
        int tap  = r >> 5;
        int hd   = r & 31;
        g_lw[idx] = lepe_w[(hd*4 + head)*9 + tap];
    }
    if (t < 128) {
        int head = t >> 5, hd = t & 31;
        g_lb[t] = lepe_b[hd*4 + head];
    }
    if (t < 64) {
        int head = t >> 4, ij = t & 15;
        g_bias[t] = bias_table[rel_idx[ij]*4 + head];
    }
}

// ---------------------------------------------------------------------------
// B chunk staging (256 threads): weights [o(128)][k(128)] -> tf32 frag-major
// ---------------------------------------------------------------------------
__device__ __forceinline__ void stage_b_chunk(uint32_t* __restrict__ Bc,
                                              const float* __restrict__ w,
                                              int c, int tid)
{
    #pragma unroll
    for (int it = 0; it < 4; ++it) {
        int i   = it*256 + tid;      // 0..1023
        int o   = i >> 3;            // 0..127
        int k4l = i & 7;
        float4 v = __ldg((const float4*)(w + (size_t)o*128) + (c*8 + k4l));
        int l = k4l >> 1, r = k4l & 1;
        uint32_t base = (uint32_t)(l*B_KSTRIDE + (o>>3)*64 + (o&7)*8 + r);
        Bc[base + 0] = cvt_tf32(v.x);
        Bc[base + 2] = cvt_tf32(v.y);
        Bc[base + 4] = cvt_tf32(v.z);
        Bc[base + 6] = cvt_tf32(v.w);
    }
}

// ---------------------------------------------------------------------------
// MMA over one 4-kstep chunk; 8 warps: warp tile 32(M) x 32(N), M total 64
// A fragment index: (kg*4 + warp_m*2 + i)
// ---------------------------------------------------------------------------
__device__ __forceinline__ void mma_chunk4(float acc[2][4][4],
                                           const uint32_t* __restrict__ As,
                                           const uint32_t* __restrict__ Bc,
                                           int ks0, int warp_m, int warp_n, int lane)
{
    #pragma unroll
    for (int l = 0; l < 4; ++l) {
        const int kg = ks0 + l;
        uint4 a[2];
        #pragma unroll
        for (int i = 0; i < 2; ++i) {
            uint32_t u = (uint32_t)((kg*4 + warp_m*2 + i)*32 + lane);
            u ^= (u >> 3) & 7;
            a[i] = *(const uint4*)(As + (size_t)u*4);
        }
        uint2 bf[4];
        #pragma unroll
        for (int j = 0; j < 4; ++j)
            bf[j] = *(const uint2*)(Bc + l*B_KSTRIDE + (warp_n*4 + j)*64 + lane*2);
        #pragma unroll
        for (int i = 0; i < 2; ++i)
            #pragma unroll
            for (int j = 0; j < 4; ++j)
                mma_tf32(acc[i][j], a[i], bf[j]);
    }
}

__device__ __forceinline__ void acc_zero(float acc[2][4][4]) {
    #pragma unroll
    for (int i = 0; i < 2; ++i)
        #pragma unroll
        for (int j = 0; j < 4; ++j)
            #pragma unroll
            for (int e = 0; e < 4; ++e) acc[i][j][e] = 0.0f;
}

// acc -> Cs[head(4)][pix 64][36]
__device__ __forceinline__ void write_c_all(const float acc[2][4][4],
                                            float* __restrict__ Cs,
                                            int warp_m, int warp_n, int lane)
{
    const int g  = lane >> 2;
    const int tg = lane & 3;
    #pragma unroll
    for (int i = 0; i < 2; ++i) {
        int pl = warp_m*32 + i*16 + g;
        #pragma unroll
        for (int j = 0; j < 4; ++j) {
            int o0 = warp_n*32 + j*8 + 2*tg;
            int h0 = o0 & 3, h1 = (o0 + 1) & 3;
            int hd = o0 >> 2;
            Cs[(h0*64 + pl    )*36 + hd] = acc[i][j][0];
            Cs[(h1*64 + pl    )*36 + hd] = acc[i][j][1];
            Cs[(h0*64 + pl + 8)*36 + hd] = acc[i][j][2];
            Cs[(h1*64 + pl + 8)*36 + hd] = acc[i][j][3];
        }
    }
}

// acc -> Qs[hh(2)][pix 64][36] for one head-pair
__device__ __forceinline__ void write_c_pair(const float acc[2][4][4],
                                             float* __restrict__ Qs, int pair,
                                             int warp_m, int warp_n, int lane)
{
    const int g  = lane >> 2;
    const int tg = lane & 3;
    if ((tg & 1) != pair) return;
    #pragma unroll
    for (int i = 0; i < 2; ++i) {
        int pl = warp_m*32 + i*16 + g;
        #pragma unroll
        for (int j = 0; j < 4; ++j) {
            int o0 = warp_n*32 + j*8 + 2*tg;
            int hd = o0 >> 2;
            Qs[(0*64 + pl    )*36 + hd] = acc[i][j][0];
            Qs[(1*64 + pl    )*36 + hd] = acc[i][j][1];
            Qs[(0*64 + pl + 8)*36 + hd] = acc[i][j][2];
            Qs[(1*64 + pl + 8)*36 + hd] = acc[i][j][3];
        }
    }
}

// ---------------------------------------------------------------------------
// Kernel 1: v = 1x1 conv (tf32 GEMM), M=64 linear blocks, 2 CTAs/SM
// ---------------------------------------------------------------------------
__global__ void __launch_bounds__(256, 2)
v_kernel(const float* __restrict__ x, const float* __restrict__ qkv_w)
{
    extern __shared__ __align__(16) float smf[];
    uint32_t* As = (uint32_t*)smf;
    uint32_t* Bc = (uint32_t*)(smf + SMF_VB);
    float*    Cs = smf + SMF_VC;

    const int tid    = threadIdx.x;
    const int lane   = tid & 31;
    const int wid    = tid >> 5;
    const int warp_m = wid >> 2;    // 0..1
    const int warp_n = wid & 3;     // 0..3
    const int n      = blockIdx.y;
    const int half   = n >> 2;
    const int b      = n & 3;
    const int p0     = blockIdx.x * 64;
    const size_t n4  = (size_t)n * 4;

    // stage A (linear 64-pixel block)
    {
        const int pix = tid & 63;
        const int kh  = tid >> 6;    // 0..3
        const float* xb = x + ((size_t)(b*256 + half*128 + kh*32)) * NPIX + p0 + pix;
        const int mtile   = pix >> 4;
        const int g       = pix & 7;
        const int rowhalf = (pix >> 3) & 1;
        #pragma unroll 8
        for (int k2 = 0; k2 < 32; ++k2) {
            int k = kh*32 + k2;
            float v = __ldg(xb + (size_t)k2 * NPIX);
            int kstep = k >> 3, tg = k & 3, colhalf = (k >> 2) & 1;
            uint32_t u = (uint32_t)((kstep*4 + mtile)*32 + g*4 + tg);
            u ^= (u >> 3) & 7;
            As[u*4 + colhalf*2 + rowhalf] = cvt_tf32(v);
        }
    }

    float acc[2][4][4];
    acc_zero(acc);
    #pragma unroll 1
    for (int c = 0; c < 4; ++c) {
        stage_b_chunk(Bc, qkv_w + 32768, c, tid);
        __syncthreads();
        mma_chunk4(acc, As, Bc, c*4, warp_m, warp_n, lane);
        __syncthreads();
    }

    write_c_all(acc, Cs, warp_m, warp_n, lane);
    __syncthreads();

    // drain: one (head,pixel) row per thread, 8 x STG.128 linear
    {
        int h   = tid >> 6;
        int pix = tid & 63;
        const float4* src = (const float4*)(Cs + (size_t)(h*64 + pix)*36);
        float4* d = (float4*)(g_v + ((n4 + h)*NPIX + (size_t)(p0 + pix))*32);
        #pragma unroll
        for (int c = 0; c < 8; ++c) d[c] = src[c];
    }
}

// ---------------------------------------------------------------------------
// Kernel 2: fused q,k GEMM + window attention + LePE.
// CTA = 2 rows x 32 cols, 256 threads, 2 CTAs/SM.
// ---------------------------------------------------------------------------
__global__ void __launch_bounds__(256, 2)
qkv_attn_kernel(const float* __restrict__ x, const float* __restrict__ qkv_w,
                float* __restrict__ out)
{
    extern __shared__ __align__(16) float smf[];
    uint32_t* As = (uint32_t*)smf;
    uint32_t* Bc = (uint32_t*)(smf + SMF_B);
    float*    Ks = smf + SMF_K;
    float*    Qs = smf + SMF_Q;

    const int tid    = threadIdx.x;
    const int lane   = tid & 31;
    const int wid    = tid >> 5;
    const int warp_m = wid >> 2;    // 0..1
    const int warp_n = wid & 3;     // 0..3
    const int n      = blockIdx.z;
    const int half   = n >> 2;
    const int b      = n & 3;
    const int x0     = blockIdx.x * 32;
    const int y0     = blockIdx.y * 2;

    // stage per-head constants
    for (int idx = tid; idx < 1152; idx += 256) smf[SMF_LW + idx] = g_lw[idx];
    if (tid < 128)       smf[SMF_LB + tid] = g_lb[tid];
    else if (tid < 192)  smf[SMF_BIAS + tid - 128] = g_bias[tid - 128];

    // stage A: interior 2x32 tile, fragment-major tf32 + swizzle
    {
        const int pix = tid & 63;                 // row*32 + col
        const int kh  = tid >> 6;                 // 0..3
        const int gy  = y0 + (pix >> 5);
        const int gx  = x0 + (pix & 31);
        const float* xb = x + ((size_t)(b*256 + half*128 + kh*32)) * NPIX
                            + (size_t)gy*WW + gx;
        const int mtile   = pix >> 4;
        const int g       = pix & 7;
        const int rowhalf = (pix >> 3) & 1;
        #pragma unroll 8
        for (int k2 = 0; k2 < 32; ++k2) {
            int k = kh*32 + k2;
            float v = __ldg(xb + (size_t)k2 * NPIX);
            int kstep = k >> 3, tg = k & 3, colhalf = (k >> 2) & 1;
            uint32_t u = (uint32_t)((kstep*4 + mtile)*32 + g*4 + tg);
            u ^= (u >> 3) & 7;
            As[u*4 + colhalf*2 + rowhalf] = cvt_tf32(v);
        }
    }

    float acc[2][4][4];

    // ---- k pass (weights at +16384) ----
    acc_zero(acc);
    #pragma unroll 1
    for (int c = 0; c < 4; ++c) {
        stage_b_chunk(Bc, qkv_w + 16384, c, tid);
        __syncthreads();
        mma_chunk4(acc, As, Bc, c*4, warp_m, warp_n, lane);
        __syncthreads();
    }
    write_c_all(acc, Ks, warp_m, warp_n, lane);

    // ---- q pass (weights at +0) ----
    acc_zero(acc);
    #pragma unroll 1
    for (int c = 0; c < 4; ++c) {
        stage_b_chunk(Bc, qkv_w, c, tid);
        __syncthreads();
        mma_chunk4(acc, As, Bc, c*4, warp_m, warp_n, lane);
        __syncthreads();
    }
    // A and B regions now dead -> vs overlay allowed

    const float scale = 0.17677669529663687f;  // 1/sqrt(32)
    const size_t n4 = (size_t)n * 4;

    #pragma unroll 1
    for (int pair = 0; pair < 2; ++pair) {
        // park this pair's q
        write_c_pair(acc, Qs, pair, warp_m, warp_n, lane);

        // stage vs[hh(2)][4x34 halo][36] from g_v (overlaying A/B region)
        for (int idx = tid; idx < 2*136*8; idx += 256) {
            int hh  = idx / 1088;
            int rem = idx - hh*1088;
            int pix = rem >> 3;
            int c8  = rem & 7;
            int py  = pix / 34;
            int px  = pix - py*34;
            int gy  = y0 - 1 + py;
            int gx  = x0 - 1 + px;
            float4 vv = make_float4(0.f, 0.f, 0.f, 0.f);
            if (gy >= 0 && gy < HH && gx >= 0 && gx < WW)
                vv = __ldg((const float4*)(g_v +
                        ((n4 + pair*2 + hh)*NPIX + (size_t)gy*WW + gx)*32) + c8);
            *(float4*)(smf + (size_t)(hh*136 + pix)*36 + c8*4) = vv;
        }
        __syncthreads();

        // attention + lepe: 128 active threads = 2 heads x 16 windows x 4 tokens
        if (tid < 128) {
            const int hp   = tid >> 6;
            const int t    = tid & 63;
            const int w    = t >> 2;
            const int i    = t & 3;
            const int head = pair*2 + hp;
            const int sy   = i >> 1, sx = i & 1;
            const int lx   = 2*w + sx;
            const int gy   = y0 + sy, gx = x0 + lx;

            // q (32 ch) from Qs
            const float* qp = Qs + (size_t)(hp*64 + sy*32 + lx)*36;
            float qr[32];
            #pragma unroll
            for (int c8 = 0; c8 < 8; ++c8) {
                float4 qv = *(const float4*)(qp + c8*4);
                qr[c8*4+0] = qv.x; qr[c8*4+1] = qv.y;
                qr[c8*4+2] = qv.z; qr[c8*4+3] = qv.w;
            }
            // logits vs 4 window tokens
            float lg[4];
            #pragma unroll
            for (int j = 0; j < 4; ++j) {
                const float* kp = Ks + (size_t)(head*64 + (j>>1)*32 + 2*w + (j&1))*36;
                float s = 0.f;
                #pragma unroll
                for (int c8 = 0; c8 < 8; ++c8) {
                    float4 kv = *(const float4*)(kp + c8*4);
                    s = fmaf(qr[c8*4+0], kv.x, s);
                    s = fmaf(qr[c8*4+1], kv.y, s);
                    s = fmaf(qr[c8*4+2], kv.z, s);
                    s = fmaf(qr[c8*4+3], kv.w, s);
                }
                lg[j] = s*scale + smf[SMF_BIAS + head*16 + i*4 + j];
            }
            float m  = fmaxf(fmaxf(lg[0], lg[1]), fmaxf(lg[2], lg[3]));
            float a0 = expf(lg[0] - m);
            float a1 = expf(lg[1] - m);
            float a2 = expf(lg[2] - m);
            float a3 = expf(lg[3] - m);
            float inv = 1.0f / (a0 + a1 + a2 + a3);
            a0 *= inv; a1 *= inv; a2 *= inv; a3 *= inv;

            const float* vsb = smf + (size_t)hp*136*36;
            const float* vj0 = vsb + (size_t)(1*34 + 1 + 2*w    )*36;
            const float* vj1 = vsb + (size_t)(1*34 + 1 + 2*w + 1)*36;
            const float* vj2 = vsb + (size_t)(2*34 + 1 + 2*w    )*36;
            const float* vj3 = vsb + (size_t)(2*34 + 1 + 2*w + 1)*36;
            const float* lwp = smf + SMF_LW + head*288;
            const float* lbp = smf + SMF_LB + head*32;

            const size_t ob = ((size_t)(b*256 + half*128 + head)) * NPIX
                            + (size_t)gy*WW + gx;
            #pragma unroll
            for (int c8 = 0; c8 < 8; ++c8) {
                float4 v0 = *(const float4*)(vj0 + c8*4);
                float4 v1 = *(const float4*)(vj1 + c8*4);
                float4 v2 = *(const float4*)(vj2 + c8*4);
                float4 v3 = *(const float4*)(vj3 + c8*4);

                float ox = a0*v0.x; ox = fmaf(a1, v1.x, ox); ox = fmaf(a2, v2.x, ox); ox = fmaf(a3, v3.x, ox);
                float oy = a0*v0.y; oy = fmaf(a1, v1.y, oy); oy = fmaf(a2, v2.y, oy); oy = fmaf(a3, v3.y, oy);
                float oz = a0*v0.z; oz = fmaf(a1, v1.z, oz); oz = fmaf(a2, v2.z, oz); oz = fmaf(a3, v3.z, oz);
                float ow = a0*v0.w; ow = fmaf(a1, v1.w, ow); ow = fmaf(a2, v2.w, ow); ow = fmaf(a3, v3.w, ow);

                // LePE 3x3 around (sy, lx); halo origin at (-1,-1)
                #pragma unroll
                for (int tp = 0; tp < 9; ++tp) {
                    int dy = tp / 3, dx = tp - dy*3;
                    float4 vv = *(const float4*)(vsb +
                        (size_t)((sy + dy)*34 + lx + dx)*36 + c8*4);
                    float4 wv = *(const float4*)(lwp + tp*32 + c8*4);
                    ox = fmaf(wv.x, vv.x, ox);
                    oy = fmaf(wv.y, vv.y, oy);
                    oz = fmaf(wv.z, vv.z, oz);
                    ow = fmaf(wv.w, vv.w, ow);
                }
                float4 bb = *(const float4*)(lbp + c8*4);
                ox += bb.x; oy += bb.y; oz += bb.z; ow += bb.w;

                out[ob + (size_t)(c8*4 + 0) * 4 * NPIX] = ox;
                out[ob + (size_t)(c8*4 + 1) * 4 * NPIX] = oy;
                out[ob + (size_t)(c8*4 + 2) * 4 * NPIX] = oz;
                out[ob + (size_t)(c8*4 + 3) * 4 * NPIX] = ow;
            }
        }
        __syncthreads();   // pair reads done before Qs/vs rewritten
    }
}

// ---------------------------------------------------------------------------
// Launcher
// ---------------------------------------------------------------------------
extern "C" void kernel_launch(void* const* d_in, const int* in_sizes, int n_in,
                              void* d_out, int out_size)
{
    const float* x          = (const float*)d_in[0];
    const float* qkv_w      = (const float*)d_in[1];
    const float* lepe_w     = (const float*)d_in[2];
    const float* lepe_b     = (const float*)d_in[3];
    const float* bias_table = (const float*)d_in[4];
    const int*   rel_idx    = (const int*)  d_in[5];
    float* out = (float*)d_out;

    cudaFuncSetAttribute(v_kernel, cudaFuncAttributeMaxDynamicSharedMemorySize, SM_TOT_V);
    cudaFuncSetAttribute(qkv_attn_kernel, cudaFuncAttributeMaxDynamicSharedMemorySize, SM_TOT_F);

    prep_kernel<<<1, 256>>>(lepe_w, lepe_b, bias_table, rel_idx);

    dim3 gv(NPIX/64, NB);            // 576 x 8
    v_kernel<<<gv, 256, SM_TOT_V>>>(x, qkv_w);

    dim3 gf(WW/32, HH/2, NB);        // 6 x 96 x 8
    qkv_attn_kernel<<<gf, 256, SM_TOT_F>>>(x, qkv_w, out);
}

// round 8
// speedup vs baseline: 1.7984x; 1.1968x over previous
#include <cuda_runtime.h>
#include <cuda_fp16.h>
#include <cstdint>

// ---------------------------------------------------------------------------
// Problem constants
// ---------------------------------------------------------------------------
#define HH    192
#define WW    192
#define NPIX  (HH*WW)          // 36864
#define NB    8                // 2 halves * batch 4
#define NHEAD 4

// ---------------------------------------------------------------------------
// Device scratch: only v round-trips.
// v layout: [n(8)][head(4)][pixel(36864)][hd(32)]
// ---------------------------------------------------------------------------
__device__ float g_v[8*4*NPIX*32];
__device__ float g_lw[4*9*32];      // [head][tap][hd] lepe weights
__device__ float g_lb[4*32];        // [head][hd] lepe bias
__device__ float g_bias[4*16];      // [head][i*4+j] attention bias

// ---------------------------------------------------------------------------
// fp16 helpers (base-ISA mma.sync m16n8k16)
// ---------------------------------------------------------------------------
__device__ __forceinline__ uint32_t pkh2(float a, float b) {
    __half2 h = __floats2half2_rn(a, b);   // low half = a
    return *reinterpret_cast<uint32_t*>(&h);
}
__device__ __forceinline__ void mma_f16(float* c, const uint4& a, const uint2& b) {
    asm volatile(
        "mma.sync.aligned.m16n8k16.row.col.f32.f16.f16.f32 "
        "{%0,%1,%2,%3}, {%4,%5,%6,%7}, {%8,%9}, {%0,%1,%2,%3};"
        : "+f"(c[0]), "+f"(c[1]), "+f"(c[2]), "+f"(c[3])
        : "r"(a.x), "r"(a.y), "r"(a.z), "r"(a.w), "r"(b.x), "r"(b.y));
}

#define B_KSTRIDE 1026   // b32 per kstep block (16 ntiles x 64 + 2 pad)

// ---- fused-kernel smem map (b32/float units) --------------------------------
// [0 .. 4096)       A tile (64 pix x 128 k fp16, fragment-major + swizzle)
// [4096 .. 8200)    B chunk (4 ksteps of k16)
// [8200 .. 9792)    pad (vs overlay needs [0, 9792) = 2*136*36)
// [9792 .. 19008)   Ks: 4 heads x 64 pix x 36 (fp32)
// [19008 .. 23616)  Qs: 2 heads x 64 pix x 36 (fp32)
// [23616 .. 24768)  lepe weights
// [24768 .. 24896)  lepe bias
// [24896 .. 24960)  attn bias
#define SMF_B    4096
#define SMF_K    9792
#define SMF_Q    19008
#define SMF_LW   23616
#define SMF_LB   24768
#define SMF_BIAS 24896
#define SM_TOT_F (24960*4)     // 99840 B -> 2 CTAs/SM

// ---- v-kernel smem map -------------------------------------------------------
// [0..4096) A   [4096..8200) B chunk   [8200..17416) Cs (4 x 64 x 36 fp32)
#define SMF_VB  4096
#define SMF_VC  8200
#define SM_TOT_V (17416*4)     // 69664 B -> 3 CTAs/SM

// ---------------------------------------------------------------------------
// Kernel 0: lepe / bias re-layout (tiny)
// ---------------------------------------------------------------------------
__global__ void prep_kernel(const float* __restrict__ lepe_w,
                            const float* __restrict__ lepe_b,
                            const float* __restrict__ bias_table,
                            const int*   __restrict__ rel_idx)
{
    int t = threadIdx.x;
    for (int idx = t; idx < 4*9*32; idx += 256) {
        int head = idx / 288;
        int r    = idx % 288;
        int tap  = r >> 5;
        int hd   = r & 31;
        g_lw[idx] = lepe_w[(hd*4 + head)*9 + tap];
    }
    if (t < 128) {
        int head = t >> 5, hd = t & 31;
        g_lb[t] = lepe_b[hd*4 + head];
    }
    if (t < 64) {
        int head = t >> 4, ij = t & 15;
        g_bias[t] = bias_table[rel_idx[ij]*4 + head];
    }
}

// ---------------------------------------------------------------------------
// B chunk staging (256 threads): weights [o(128)][k(128)] fp32 -> fp16 frag
// chunk c covers k = c*64 .. c*64+63 (4 ksteps of 16)
// ---------------------------------------------------------------------------
__device__ __forceinline__ void stage_b_chunk(uint32_t* __restrict__ Bc,
                                              const float* __restrict__ w,
                                              int c, int tid)
{
    #pragma unroll
    for (int it = 0; it < 8; ++it) {
        int i   = it*256 + tid;      // 0..2047
        int o   = i >> 4;            // 0..127
        int k4l = i & 15;            // float4 index within 64-k chunk
        float4 v = __ldg((const float4*)(w + (size_t)o*128) + (c*16 + k4l));
        int ksl = k4l >> 2;          // kstep within chunk
        int kc  = (k4l & 3) * 4;     // col within k16
        int tg0 = (kc >> 1) & 3;     // 0 or 2
        int r   = kc >> 3;           // b-reg 0/1
        uint32_t base = (uint32_t)(ksl*B_KSTRIDE + (o>>3)*64 + ((o&7)*4 + tg0)*2 + r);
        Bc[base    ] = pkh2(v.x, v.y);   // tg0
        Bc[base + 2] = pkh2(v.z, v.w);   // tg0+1
    }
}

// ---------------------------------------------------------------------------
// MMA over one 4-kstep chunk; 8 warps: warp tile 32(M) x 32(N), M total 64
// A fragment index: (kg*4 + warp_m*2 + i), kg = global kstep 0..7
// ---------------------------------------------------------------------------
__device__ __forceinline__ void mma_chunk4(float acc[2][4][4],
                                           const uint32_t* __restrict__ As,
                                           const uint32_t* __restrict__ Bc,
                                           int ks0, int warp_m, int warp_n, int lane)
{
    #pragma unroll
    for (int l = 0; l < 4; ++l) {
        const int kg = ks0 + l;
        uint4 a[2];
        #pragma unroll
        for (int i = 0; i < 2; ++i) {
            uint32_t u = (uint32_t)((kg*4 + warp_m*2 + i)*32 + lane);
            u ^= (u >> 3) & 7;
            a[i] = *(const uint4*)(As + (size_t)u*4);
        }
        uint2 bf[4];
        #pragma unroll
        for (int j = 0; j < 4; ++j)
            bf[j] = *(const uint2*)(Bc + l*B_KSTRIDE + (warp_n*4 + j)*64 + lane*2);
        #pragma unroll
        for (int i = 0; i < 2; ++i)
            #pragma unroll
            for (int j = 0; j < 4; ++j)
                mma_f16(acc[i][j], a[i], bf[j]);
    }
}

__device__ __forceinline__ void acc_zero(float acc[2][4][4]) {
    #pragma unroll
    for (int i = 0; i < 2; ++i)
        #pragma unroll
        for (int j = 0; j < 4; ++j)
            #pragma unroll
            for (int e = 0; e < 4; ++e) acc[i][j][e] = 0.0f;
}

// acc -> Cs[head(4)][pix 64][36]
__device__ __forceinline__ void write_c_all(const float acc[2][4][4],
                                            float* __restrict__ Cs,
                                            int warp_m, int warp_n, int lane)
{
    const int g  = lane >> 2;
    const int tg = lane & 3;
    #pragma unroll
    for (int i = 0; i < 2; ++i) {
        int pl = warp_m*32 + i*16 + g;
        #pragma unroll
        for (int j = 0; j < 4; ++j) {
            int o0 = warp_n*32 + j*8 + 2*tg;
            int h0 = o0 & 3, h1 = (o0 + 1) & 3;
            int hd = o0 >> 2;
            Cs[(h0*64 + pl    )*36 + hd] = acc[i][j][0];
            Cs[(h1*64 + pl    )*36 + hd] = acc[i][j][1];
            Cs[(h0*64 + pl + 8)*36 + hd] = acc[i][j][2];
            Cs[(h1*64 + pl + 8)*36 + hd] = acc[i][j][3];
        }
    }
}

// acc -> Qs[hh(2)][pix 64][36] for one head-pair
__device__ __forceinline__ void write_c_pair(const float acc[2][4][4],
                                             float* __restrict__ Qs, int pair,
                                             int warp_m, int warp_n, int lane)
{
    const int g  = lane >> 2;
    const int tg = lane & 3;
    if ((tg & 1) != pair) return;
    #pragma unroll
    for (int i = 0; i < 2; ++i) {
        int pl = warp_m*32 + i*16 + g;
        #pragma unroll
        for (int j = 0; j < 4; ++j) {
            int o0 = warp_n*32 + j*8 + 2*tg;
            int hd = o0 >> 2;
            Qs[(0*64 + pl    )*36 + hd] = acc[i][j][0];
            Qs[(1*64 + pl    )*36 + hd] = acc[i][j][1];
            Qs[(0*64 + pl + 8)*36 + hd] = acc[i][j][2];
            Qs[(1*64 + pl + 8)*36 + hd] = acc[i][j][3];
        }
    }
}

// ---------------------------------------------------------------------------
// A staging: 64 pixels x 128 k -> fp16 fragment-major + swizzle.
// Thread owns one pixel column, 32 consecutive channels (pairs pack locally).
// ---------------------------------------------------------------------------
__device__ __forceinline__ void stage_a(uint32_t* __restrict__ As,
                                        const float* __restrict__ xb,
                                        int pix, int kh)
{
    const int mtile   = pix >> 4;
    const int g       = pix & 7;
    const int rowhalf = (pix >> 3) & 1;
    #pragma unroll 4
    for (int k2 = 0; k2 < 32; k2 += 2) {
        int k = kh*32 + k2;
        float f0 = __ldg(xb + (size_t)k2 * NPIX);
        float f1 = __ldg(xb + (size_t)(k2+1) * NPIX);
        int kstep = k >> 4;
        int kc    = k & 15;
        int colhalf = kc >> 3;
        int tg      = (kc >> 1) & 3;
        uint32_t u = (uint32_t)((kstep*4 + mtile)*32 + g*4 + tg);
        u ^= (u >> 3) & 7;
        As[u*4 + colhalf*2 + rowhalf] = pkh2(f0, f1);
    }
}

// ---------------------------------------------------------------------------
// Kernel 1: v = 1x1 conv (fp16 GEMM), M=64 linear blocks, 3 CTAs/SM
// ---------------------------------------------------------------------------
__global__ void __launch_bounds__(256, 3)
v_kernel(const float* __restrict__ x, const float* __restrict__ qkv_w)
{
    extern __shared__ __align__(16) float smf[];
    uint32_t* As = (uint32_t*)smf;
    uint32_t* Bc = (uint32_t*)(smf + SMF_VB);
    float*    Cs = smf + SMF_VC;

    const int tid    = threadIdx.x;
    const int lane   = tid & 31;
    const int wid    = tid >> 5;
    const int warp_m = wid >> 2;    // 0..1
    const int warp_n = wid & 3;     // 0..3
    const int n      = blockIdx.y;
    const int half   = n >> 2;
    const int b      = n & 3;
    const int p0     = blockIdx.x * 64;
    const size_t n4  = (size_t)n * 4;

    {
        const int pix = tid & 63;
        const int kh  = tid >> 6;
        const float* xb = x + ((size_t)(b*256 + half*128 + kh*32)) * NPIX + p0 + pix;
        stage_a(As, xb, pix, kh);
    }

    float acc[2][4][4];
    acc_zero(acc);
    #pragma unroll 1
    for (int c = 0; c < 2; ++c) {
        stage_b_chunk(Bc, qkv_w + 32768, c, tid);
        __syncthreads();
        mma_chunk4(acc, As, Bc, c*4, warp_m, warp_n, lane);
        __syncthreads();
    }

    write_c_all(acc, Cs, warp_m, warp_n, lane);
    __syncthreads();

    // drain: one (head,pixel) row per thread, 8 x STG.128 linear
    {
        int h   = tid >> 6;
        int pix = tid & 63;
        const float4* src = (const float4*)(Cs + (size_t)(h*64 + pix)*36);
        float4* d = (float4*)(g_v + ((n4 + h)*NPIX + (size_t)(p0 + pix))*32);
        #pragma unroll
        for (int c = 0; c < 8; ++c) d[c] = src[c];
    }
}

// ---------------------------------------------------------------------------
// Kernel 2: fused q,k GEMM + window attention + LePE.
// CTA = 2 rows x 32 cols, 256 threads, 2 CTAs/SM.
// ---------------------------------------------------------------------------
__global__ void __launch_bounds__(256, 2)
qkv_attn_kernel(const float* __restrict__ x, const float* __restrict__ qkv_w,
                float* __restrict__ out)
{
    extern __shared__ __align__(16) float smf[];
    uint32_t* As = (uint32_t*)smf;
    uint32_t* Bc = (uint32_t*)(smf + SMF_B);
    float*    Ks = smf + SMF_K;
    float*    Qs = smf + SMF_Q;

    const int tid    = threadIdx.x;
    const int lane   = tid & 31;
    const int wid    = tid >> 5;
    const int warp_m = wid >> 2;    // 0..1
    const int warp_n = wid & 3;     // 0..3
    const int n      = blockIdx.z;
    const int half   = n >> 2;
    const int b      = n & 3;
    const int x0     = blockIdx.x * 32;
    const int y0     = blockIdx.y * 2;

    // stage per-head constants
    for (int idx = tid; idx < 1152; idx += 256) smf[SMF_LW + idx] = g_lw[idx];
    if (tid < 128)       smf[SMF_LB + tid] = g_lb[tid];
    else if (tid < 192)  smf[SMF_BIAS + tid - 128] = g_bias[tid - 128];

    // stage A: interior 2x32 tile
    {
        const int pix = tid & 63;                 // row*32 + col
        const int kh  = tid >> 6;
        const int gy  = y0 + (pix >> 5);
        const int gx  = x0 + (pix & 31);
        const float* xb = x + ((size_t)(b*256 + half*128 + kh*32)) * NPIX
                            + (size_t)gy*WW + gx;
        stage_a(As, xb, pix, kh);
    }

    float acc[2][4][4];

    // ---- k pass (weights at +16384) ----
    acc_zero(acc);
    #pragma unroll 1
    for (int c = 0; c < 2; ++c) {
        stage_b_chunk(Bc, qkv_w + 16384, c, tid);
        __syncthreads();
        mma_chunk4(acc, As, Bc, c*4, warp_m, warp_n, lane);
        __syncthreads();
    }
    write_c_all(acc, Ks, warp_m, warp_n, lane);

    // ---- q pass (weights at +0) ----
    acc_zero(acc);
    #pragma unroll 1
    for (int c = 0; c < 2; ++c) {
        stage_b_chunk(Bc, qkv_w, c, tid);
        __syncthreads();
        mma_chunk4(acc, As, Bc, c*4, warp_m, warp_n, lane);
        __syncthreads();
    }
    // A and B regions now dead -> vs overlay allowed

    const float scale = 0.17677669529663687f;  // 1/sqrt(32)
    const size_t n4 = (size_t)n * 4;

    #pragma unroll 1
    for (int pair = 0; pair < 2; ++pair) {
        // park this pair's q
        write_c_pair(acc, Qs, pair, warp_m, warp_n, lane);

        // stage vs[hh(2)][4x34 halo][36] from g_v (overlaying A/B region)
        for (int idx = tid; idx < 2*136*8; idx += 256) {
            int hh  = idx / 1088;
            int rem = idx - hh*1088;
            int pix = rem >> 3;
            int c8  = rem & 7;
            int py  = pix / 34;
            int px  = pix - py*34;
            int gy  = y0 - 1 + py;
            int gx  = x0 - 1 + px;
            float4 vv = make_float4(0.f, 0.f, 0.f, 0.f);
            if (gy >= 0 && gy < HH && gx >= 0 && gx < WW)
                vv = __ldg((const float4*)(g_v +
                        ((n4 + pair*2 + hh)*NPIX + (size_t)gy*WW + gx)*32) + c8);
            *(float4*)(smf + (size_t)(hh*136 + pix)*36 + c8*4) = vv;
        }
        __syncthreads();

        // attention + lepe: 128 active threads = 2 heads x 16 windows x 4 tokens
        if (tid < 128) {
            const int hp   = tid >> 6;
            const int t    = tid & 63;
            const int w    = t >> 2;
            const int i    = t & 3;
            const int head = pair*2 + hp;
            const int sy   = i >> 1, sx = i & 1;
            const int lx   = 2*w + sx;
            const int gy   = y0 + sy, gx = x0 + lx;

            const float* qp = Qs + (size_t)(hp*64 + sy*32 + lx)*36;
            float qr[32];
            #pragma unroll
            for (int c8 = 0; c8 < 8; ++c8) {
                float4 qv = *(const float4*)(qp + c8*4);
                qr[c8*4+0] = qv.x; qr[c8*4+1] = qv.y;
                qr[c8*4+2] = qv.z; qr[c8*4+3] = qv.w;
            }
            float lg[4];
            #pragma unroll
            for (int j = 0; j < 4; ++j) {
                const float* kp = Ks + (size_t)(head*64 + (j>>1)*32 + 2*w + (j&1))*36;
                float s = 0.f;
                #pragma unroll
                for (int c8 = 0; c8 < 8; ++c8) {
                    float4 kv = *(const float4*)(kp + c8*4);
                    s = fmaf(qr[c8*4+0], kv.x, s);
                    s = fmaf(qr[c8*4+1], kv.y, s);
                    s = fmaf(qr[c8*4+2], kv.z, s);
                    s = fmaf(qr[c8*4+3], kv.w, s);
                }
                lg[j] = s*scale + smf[SMF_BIAS + head*16 + i*4 + j];
            }
            float m  = fmaxf(fmaxf(lg[0], lg[1]), fmaxf(lg[2], lg[3]));
            float a0 = expf(lg[0] - m);
            float a1 = expf(lg[1] - m);
            float a2 = expf(lg[2] - m);
            float a3 = expf(lg[3] - m);
            float inv = 1.0f / (a0 + a1 + a2 + a3);
            a0 *= inv; a1 *= inv; a2 *= inv; a3 *= inv;

            const float* vsb = smf + (size_t)hp*136*36;
            const float* vj0 = vsb + (size_t)(1*34 + 1 + 2*w    )*36;
            const float* vj1 = vsb + (size_t)(1*34 + 1 + 2*w + 1)*36;
            const float* vj2 = vsb + (size_t)(2*34 + 1 + 2*w    )*36;
            const float* vj3 = vsb + (size_t)(2*34 + 1 + 2*w + 1)*36;
            const float* lwp = smf + SMF_LW + head*288;
            const float* lbp = smf + SMF_LB + head*32;

            const size_t ob = ((size_t)(b*256 + half*128 + head)) * NPIX
                            + (size_t)gy*WW + gx;
            #pragma unroll
            for (int c8 = 0; c8 < 8; ++c8) {
                float4 v0 = *(const float4*)(vj0 + c8*4);
                float4 v1 = *(const float4*)(vj1 + c8*4);
                float4 v2 = *(const float4*)(vj2 + c8*4);
                float4 v3 = *(const float4*)(vj3 + c8*4);

                float ox = a0*v0.x; ox = fmaf(a1, v1.x, ox); ox = fmaf(a2, v2.x, ox); ox = fmaf(a3, v3.x, ox);
                float oy = a0*v0.y; oy = fmaf(a1, v1.y, oy); oy = fmaf(a2, v2.y, oy); oy = fmaf(a3, v3.y, oy);
                float oz = a0*v0.z; oz = fmaf(a1, v1.z, oz); oz = fmaf(a2, v2.z, oz); oz = fmaf(a3, v3.z, oz);
                float ow = a0*v0.w; ow = fmaf(a1, v1.w, ow); ow = fmaf(a2, v2.w, ow); ow = fmaf(a3, v3.w, ow);

                #pragma unroll
                for (int tp = 0; tp < 9; ++tp) {
                    int dy = tp / 3, dx = tp - dy*3;
                    float4 vv = *(const float4*)(vsb +
                        (size_t)((sy + dy)*34 + lx + dx)*36 + c8*4);
                    float4 wv = *(const float4*)(lwp + tp*32 + c8*4);
                    ox = fmaf(wv.x, vv.x, ox);
                    oy = fmaf(wv.y, vv.y, oy);
                    oz = fmaf(wv.z, vv.z, oz);
                    ow = fmaf(wv.w, vv.w, ow);
                }
                float4 bb = *(const float4*)(lbp + c8*4);
                ox += bb.x; oy += bb.y; oz += bb.z; ow += bb.w;

                out[ob + (size_t)(c8*4 + 0) * 4 * NPIX] = ox;
                out[ob + (size_t)(c8*4 + 1) * 4 * NPIX] = oy;
                out[ob + (size_t)(c8*4 + 2) * 4 * NPIX] = oz;
                out[ob + (size_t)(c8*4 + 3) * 4 * NPIX] = ow;
            }
        }
        __syncthreads();   // pair reads done before Qs/vs rewritten
    }
}

// ---------------------------------------------------------------------------
// Launcher
// ---------------------------------------------------------------------------
extern "C" void kernel_launch(void* const* d_in, const int* in_sizes, int n_in,
                              void* d_out, int out_size)
{
    const float* x          = (const float*)d_in[0];
    const float* qkv_w      = (const float*)d_in[1];
    const float* lepe_w     = (const float*)d_in[2];
    const float* lepe_b     = (const float*)d_in[3];
    const float* bias_table = (const float*)d_in[4];
    const int*   rel_idx    = (const int*)  d_in[5];
    float* out = (float*)d_out;

    cudaFuncSetAttribute(v_kernel, cudaFuncAttributeMaxDynamicSharedMemorySize, SM_TOT_V);
    cudaFuncSetAttribute(qkv_attn_kernel, cudaFuncAttributeMaxDynamicSharedMemorySize, SM_TOT_F);

    prep_kernel<<<1, 256>>>(lepe_w, lepe_b, bias_table, rel_idx);

    dim3 gv(NPIX/64, NB);            // 576 x 8
    v_kernel<<<gv, 256, SM_TOT_V>>>(x, qkv_w);

    dim3 gf(WW/32, HH/2, NB);        // 6 x 96 x 8
    qkv_attn_kernel<<<gf, 256, SM_TOT_F>>>(x, qkv_w, out);
}